// round 1
// baseline (speedup 1.0000x reference)
#include <cuda_runtime.h>
#include <math.h>

#define N_NODES 100000
#define ZDIM 64
#define H1 128
#define E_DEC_MAX 200000

// ---------------- scratch (static device arrays; no allocation) ----------------
__device__ float g_s1cnt[2 * N_NODES];          // interleaved {sum_x, count} per node
__device__ float g_y[N_NODES * ZDIM];           // z1 @ W_rel2
__device__ float g_r[N_NODES * ZDIM];           // z1 @ W_root2
__device__ float g_z2[N_NODES * ZDIM];          // agg2 accumulator, then z2 in-place
__device__ float g_nrep[E_DEC_MAX * ZDIM];      // z2[src]*z2[dst]

// ---------------- vector reductions (sm_90+) ----------------
static __device__ __forceinline__ void red_add_v2(float* addr, float a, float b) {
    asm volatile("red.global.add.v2.f32 [%0], {%1, %2};"
                 :: "l"(addr), "f"(a), "f"(b) : "memory");
}
static __device__ __forceinline__ void red_add_v4(float* addr, float4 v) {
    asm volatile("red.global.add.v4.f32 [%0], {%1, %2, %3, %4};"
                 :: "l"(addr), "f"(v.x), "f"(v.y), "f"(v.z), "f"(v.w) : "memory");
}

// ---------------- zero scratch (graph-replay safe) ----------------
__global__ void zero_k() {
    int i = blockIdx.x * blockDim.x + threadIdx.x;
    if (i < 2 * N_NODES) g_s1cnt[i] = 0.0f;
    if (i < N_NODES * ZDIM) g_z2[i] = 0.0f;
}

// ---------------- layer-1 edge pass: scalar segment sum + count ----------------
__global__ void edge1_k(const int* __restrict__ src, const int* __restrict__ dst,
                        const float* __restrict__ x, int E) {
    int e = blockIdx.x * blockDim.x + threadIdx.x;
    if (e >= E) return;
    int s = src[e], d = dst[e];
    red_add_v2(&g_s1cnt[2 * d], x[s], 1.0f);
}

// ---------------- per-node: z1 = relu(x*Wr1 + m*Wl1 + b1); y = z1@Wrel2, r = z1@Wroot2
__global__ void node1_k(const float* __restrict__ x,
                        const float* __restrict__ Wroot1, const float* __restrict__ Wrel1,
                        const float* __restrict__ b1,
                        const float* __restrict__ Wroot2, const float* __restrict__ Wrel2) {
    __shared__ float z1[H1];
    int i = blockIdx.x;
    int t = threadIdx.x;
    float xi = x[i];
    float2 sc = ((const float2*)g_s1cnt)[i];
    float m = sc.x / fmaxf(sc.y, 1.0f);
    z1[t] = fmaxf(xi * Wroot1[t] + m * Wrel1[t] + b1[t], 0.0f);
    __syncthreads();
    const float* __restrict__ W = (t < ZDIM) ? Wrel2 : Wroot2;
    int c = t & (ZDIM - 1);
    float acc = 0.0f;
#pragma unroll 8
    for (int k = 0; k < H1; k++) acc += z1[k] * W[k * ZDIM + c];
    if (t < ZDIM) g_y[i * ZDIM + c] = acc;
    else          g_r[i * ZDIM + c] = acc;
}

// ---------------- layer-2 edge scatter: agg2[dst] += y[src], 16 lanes x float4 ----------------
__global__ void edge2_k(const int* __restrict__ src, const int* __restrict__ dst, int E) {
    int idx = blockIdx.x * blockDim.x + threadIdx.x;
    int e = idx >> 4;
    if (e >= E) return;
    int g = idx & 15;
    int s = src[e], d = dst[e];
    float4 v = ((const float4*)g_y)[s * 16 + g];
    red_add_v4(&g_z2[d * ZDIM + g * 4], v);
}

// ---------------- z2 = relu(r + agg2/cnt + b2) (in place over agg2) ----------------
__global__ void node2_k(const float* __restrict__ b2) {
    int i = blockIdx.x * blockDim.x + threadIdx.x;
    if (i >= N_NODES * ZDIM) return;
    int n = i >> 6, c = i & 63;
    float cnt = g_s1cnt[2 * n + 1];
    float v = g_r[i] + g_z2[i] / fmaxf(cnt, 1.0f) + b2[c];
    g_z2[i] = fmaxf(v, 0.0f);
}

// ---------------- decode pair gather: node_rep = z2[src]*z2[dst] ----------------
__global__ void pair_k(const int* __restrict__ src, const int* __restrict__ dst, int E) {
    int idx = blockIdx.x * blockDim.x + threadIdx.x;
    int e = idx >> 4;
    if (e >= E) return;
    int g = idx & 15;
    int s = src[e], d = dst[e];
    float4 a = ((const float4*)g_z2)[s * 16 + g];
    float4 b = ((const float4*)g_z2)[d * 16 + g];
    float4 o;
    o.x = a.x * b.x; o.y = a.y * b.y; o.z = a.z * b.z; o.w = a.w * b.w;
    ((float4*)g_nrep)[e * 16 + g] = o;
}

// ---------------- fused decode: [E,832]@[832,128] -> relu -> @[128,5] -> softmax ----------------
// BM=64 edges, BN=128 (full), BK=32; 256 threads, 4x8 per thread.
__global__ __launch_bounds__(256)
void decode_k(const float* __restrict__ eattr,
              const float* __restrict__ W1, const float* __restrict__ bl1,
              const float* __restrict__ W2, const float* __restrict__ bl2,
              float* __restrict__ out, int E) {
    __shared__ float sm[64 * 129];   // phase1: sJ[64*32] @0, sW[32*128] @2048. phase2: sH[64][129]
    int tid = threadIdx.x;
    int e0 = blockIdx.x * 64;
    int rb = (tid >> 4) << 2;        // row base 0..60
    int cb = (tid & 15) << 3;        // col base 0..120

    float acc[4][8];
#pragma unroll
    for (int i = 0; i < 4; i++)
#pragma unroll
        for (int j = 0; j < 8; j++) acc[i][j] = 0.0f;

    for (int k0 = 0; k0 < 832; k0 += 32) {
        // load J tile: 64 rows x 32 cols (cols <64 -> node_rep, else edge_attr)
#pragma unroll
        for (int c = 0; c < 2; c++) {
            int idx = tid + c * 256;
            int row = idx >> 3, q = idx & 7;
            int col = k0 + q * 4;
            int e = e0 + row;
            float4 v;
            if (e < E) {
                if (col < 64) v = ((const float4*)g_nrep)[e * 16 + (col >> 2)];
                else          v = ((const float4*)eattr)[(size_t)e * 192 + ((col - 64) >> 2)];
            } else {
                v = make_float4(0.f, 0.f, 0.f, 0.f);
            }
            *(float4*)&sm[row * 32 + (q << 2)] = v;
        }
        // load W tile: 32 rows x 128 cols
#pragma unroll
        for (int c = 0; c < 4; c++) {
            int idx = tid + c * 256;
            int k = idx >> 5, q = idx & 31;
            float4 v = ((const float4*)W1)[(k0 + k) * 32 + q];
            *(float4*)&sm[2048 + k * 128 + (q << 2)] = v;
        }
        __syncthreads();
#pragma unroll
        for (int kk = 0; kk < 32; kk++) {
            float a[4], b[8];
#pragma unroll
            for (int i = 0; i < 4; i++) a[i] = sm[(rb + i) * 32 + kk];
#pragma unroll
            for (int j = 0; j < 8; j++) b[j] = sm[2048 + kk * 128 + cb + j];
#pragma unroll
            for (int i = 0; i < 4; i++)
#pragma unroll
                for (int j = 0; j < 8; j++) acc[i][j] += a[i] * b[j];
        }
        __syncthreads();
    }

    // epilogue phase: h = relu(acc + b_lin1) into sH[64][129]
#pragma unroll
    for (int i = 0; i < 4; i++)
#pragma unroll
        for (int j = 0; j < 8; j++)
            sm[(rb + i) * 129 + cb + j] = fmaxf(acc[i][j] + bl1[cb + j], 0.0f);
    __syncthreads();

    if (tid < 64) {
        int e = e0 + tid;
        if (e < E) {
            float l[5];
#pragma unroll
            for (int q = 0; q < 5; q++) l[q] = bl2[q];
            for (int k = 0; k < 128; k++) {
                float h = sm[tid * 129 + k];
#pragma unroll
                for (int q = 0; q < 5; q++) l[q] += h * W2[k * 5 + q];
            }
            float mx = l[0];
#pragma unroll
            for (int q = 1; q < 5; q++) mx = fmaxf(mx, l[q]);
            float s = 0.0f, ex[5];
#pragma unroll
            for (int q = 0; q < 5; q++) { ex[q] = expf(l[q] - mx); s += ex[q]; }
            float inv = 1.0f / s;
#pragma unroll
            for (int q = 0; q < 5; q++) out[e * 5 + q] = ex[q] * inv;
        }
    }
}

extern "C" void kernel_launch(void* const* d_in, const int* in_sizes, int n_in,
                              void* d_out, int out_size) {
    const float* x      = (const float*)d_in[0];
    const int*   tei    = (const int*)d_in[1];
    const int*   dei    = (const int*)d_in[2];
    const float* eattr  = (const float*)d_in[3];
    const float* Wroot1 = (const float*)d_in[4];
    const float* Wrel1  = (const float*)d_in[5];
    const float* b1     = (const float*)d_in[6];
    const float* Wroot2 = (const float*)d_in[7];
    const float* Wrel2  = (const float*)d_in[8];
    const float* b2     = (const float*)d_in[9];
    const float* W1     = (const float*)d_in[10];
    const float* bl1    = (const float*)d_in[11];
    const float* W2     = (const float*)d_in[12];
    const float* bl2    = (const float*)d_in[13];
    float* out = (float*)d_out;

    int Etr = in_sizes[1] / 2;
    int Ed  = in_sizes[2] / 2;

    // zero s1cnt + agg2
    zero_k<<<(N_NODES * ZDIM + 255) / 256, 256>>>();
    // layer-1 scalar aggregation
    edge1_k<<<(Etr + 255) / 256, 256>>>(tei, tei + Etr, x, Etr);
    // per-node: z1 -> (y, r)
    node1_k<<<N_NODES, H1>>>(x, Wroot1, Wrel1, b1, Wroot2, Wrel2);
    // layer-2 vector scatter
    {
        long threads = (long)Etr * 16;
        edge2_k<<<(int)((threads + 255) / 256), 256>>>(tei, tei + Etr, Etr);
    }
    // z2
    node2_k<<<(N_NODES * ZDIM + 255) / 256, 256>>>(b2);
    // decode pair gather
    {
        long threads = (long)Ed * 16;
        pair_k<<<(int)((threads + 255) / 256), 256>>>(dei, dei + Ed, Ed);
    }
    // fused decode GEMM + head + softmax
    decode_k<<<(Ed + 63) / 64, 256>>>(eattr, W1, bl1, W2, bl2, out, Ed);
}

// round 3
// speedup vs baseline: 1.8793x; 1.8793x over previous
#include <cuda_runtime.h>
#include <cuda_bf16.h>
#include <math.h>
#include <stdint.h>

#define N_NODES 100000
#define ZDIM 64
#define H1 128
#define E_DEC_MAX 200000
#define NB_K 26            // 832 / 32 K-steps for decode GEMM

// ---------------- scratch (static device arrays; no allocation) ----------------
__device__ float g_s1cnt[2 * N_NODES];           // interleaved {sum_x, count}
__device__ float g_y[N_NODES * ZDIM];            // z1 @ W_rel2
__device__ float g_r[N_NODES * ZDIM];            // z1 @ W_root2
__device__ float g_z2[N_NODES * ZDIM];           // agg2 accumulator, then z2 in-place
__device__ float g_nrep[E_DEC_MAX * ZDIM];       // z2[src]*z2[dst]
__device__ __nv_bfloat16 g_Bth[128 * 832];       // W1^T hi, n-major [128][832]
__device__ __nv_bfloat16 g_Btl[128 * 832];       // W1^T lo

// ---------------- PTX helpers ----------------
static __device__ __forceinline__ void red_add_v2(float* addr, float a, float b) {
    asm volatile("red.global.add.v2.f32 [%0], {%1, %2};"
                 :: "l"(addr), "f"(a), "f"(b) : "memory");
}
static __device__ __forceinline__ void red_add_v4(float* addr, float4 v) {
    asm volatile("red.global.add.v4.f32 [%0], {%1, %2, %3, %4};"
                 :: "l"(addr), "f"(v.x), "f"(v.y), "f"(v.z), "f"(v.w) : "memory");
}
static __device__ __forceinline__ uint32_t smem_u32(const void* p) {
    uint32_t a;
    asm("{ .reg .u64 t; cvta.to.shared.u64 t, %1; cvt.u32.u64 %0, t; }" : "=r"(a) : "l"(p));
    return a;
}
static __device__ __forceinline__ void ldm_x4(uint32_t* r, uint32_t addr) {
    asm volatile("ldmatrix.sync.aligned.m8n8.x4.shared.b16 {%0,%1,%2,%3}, [%4];"
                 : "=r"(r[0]), "=r"(r[1]), "=r"(r[2]), "=r"(r[3]) : "r"(addr));
}
static __device__ __forceinline__ void mma_bf16(float* c, const uint32_t* a,
                                                uint32_t b0, uint32_t b1) {
    asm volatile("mma.sync.aligned.m16n8k16.row.col.f32.bf16.bf16.f32 "
                 "{%0,%1,%2,%3}, {%4,%5,%6,%7}, {%8,%9}, {%0,%1,%2,%3};"
                 : "+f"(c[0]), "+f"(c[1]), "+f"(c[2]), "+f"(c[3])
                 : "r"(a[0]), "r"(a[1]), "r"(a[2]), "r"(a[3]), "r"(b0), "r"(b1));
}

// ---------------- zero scratch ----------------
__global__ void zero_k() {
    int i = blockIdx.x * blockDim.x + threadIdx.x;
    if (i < 2 * N_NODES) g_s1cnt[i] = 0.0f;
    if (i < N_NODES * ZDIM) g_z2[i] = 0.0f;
}

// ---------------- layer-1 edge pass ----------------
__global__ void edge1_k(const int* __restrict__ src, const int* __restrict__ dst,
                        const float* __restrict__ x, int E) {
    int e = blockIdx.x * blockDim.x + threadIdx.x;
    if (e >= E) return;
    int s = src[e], d = dst[e];
    red_add_v2(&g_s1cnt[2 * d], x[s], 1.0f);
}

// ---------------- per-node layer 1 -> (y, r) ----------------
__global__ void node1_k(const float* __restrict__ x,
                        const float* __restrict__ Wroot1, const float* __restrict__ Wrel1,
                        const float* __restrict__ b1,
                        const float* __restrict__ Wroot2, const float* __restrict__ Wrel2) {
    __shared__ float z1[H1];
    int i = blockIdx.x;
    int t = threadIdx.x;
    float xi = x[i];
    float2 sc = ((const float2*)g_s1cnt)[i];
    float m = sc.x / fmaxf(sc.y, 1.0f);
    z1[t] = fmaxf(xi * Wroot1[t] + m * Wrel1[t] + b1[t], 0.0f);
    __syncthreads();
    const float* __restrict__ W = (t < ZDIM) ? Wrel2 : Wroot2;
    int c = t & (ZDIM - 1);
    float acc = 0.0f;
#pragma unroll 8
    for (int k = 0; k < H1; k++) acc += z1[k] * W[k * ZDIM + c];
    if (t < ZDIM) g_y[i * ZDIM + c] = acc;
    else          g_r[i * ZDIM + c] = acc;
}

// ---------------- layer-2 edge scatter ----------------
__global__ void edge2_k(const int* __restrict__ src, const int* __restrict__ dst, int E) {
    int idx = blockIdx.x * blockDim.x + threadIdx.x;
    int e = idx >> 4;
    if (e >= E) return;
    int g = idx & 15;
    int s = src[e], d = dst[e];
    float4 v = ((const float4*)g_y)[s * 16 + g];
    red_add_v4(&g_z2[d * ZDIM + g * 4], v);
}

// ---------------- z2 = relu(r + agg2/cnt + b2) ----------------
__global__ void node2_k(const float* __restrict__ b2) {
    int i = blockIdx.x * blockDim.x + threadIdx.x;
    if (i >= N_NODES * ZDIM) return;
    int n = i >> 6, c = i & 63;
    float cnt = g_s1cnt[2 * n + 1];
    float v = g_r[i] + g_z2[i] / fmaxf(cnt, 1.0f) + b2[c];
    g_z2[i] = fmaxf(v, 0.0f);
}

// ---------------- decode pair gather ----------------
__global__ void pair_k(const int* __restrict__ src, const int* __restrict__ dst, int E) {
    int idx = blockIdx.x * blockDim.x + threadIdx.x;
    int e = idx >> 4;
    if (e >= E) return;
    int g = idx & 15;
    int s = src[e], d = dst[e];
    float4 a = ((const float4*)g_z2)[s * 16 + g];
    float4 b = ((const float4*)g_z2)[d * 16 + g];
    float4 o;
    o.x = a.x * b.x; o.y = a.y * b.y; o.z = a.z * b.z; o.w = a.w * b.w;
    ((float4*)g_nrep)[e * 16 + g] = o;
}

// ---------------- W1^T bf16 hi/lo split (n-major [128][832]) ----------------
__global__ void prepB_k(const float* __restrict__ W1) {
    int i = blockIdx.x * blockDim.x + threadIdx.x;
    if (i >= 128 * 832) return;
    int n = i / 832, k = i % 832;
    float w = W1[k * 128 + n];
    __nv_bfloat16 hi = __float2bfloat16(w);
    __nv_bfloat16 lo = __float2bfloat16(w - __bfloat162float(hi));
    g_Bth[i] = hi;
    g_Btl[i] = lo;
}

// ---------------- split 8 fp32 -> bf16 hi/lo uint4 ----------------
static __device__ __forceinline__ void split8(float4 v0, float4 v1, uint4& hi, uint4& lo) {
    float f[8] = {v0.x, v0.y, v0.z, v0.w, v1.x, v1.y, v1.z, v1.w};
    uint32_t h[4], l[4];
#pragma unroll
    for (int j = 0; j < 4; j++) {
        __nv_bfloat16 a = __float2bfloat16(f[2 * j]);
        __nv_bfloat16 b = __float2bfloat16(f[2 * j + 1]);
        __nv_bfloat162 hp = __halves2bfloat162(a, b);
        h[j] = *(uint32_t*)&hp;
        __nv_bfloat16 la = __float2bfloat16(f[2 * j]     - __bfloat162float(a));
        __nv_bfloat16 lb = __float2bfloat16(f[2 * j + 1] - __bfloat162float(b));
        __nv_bfloat162 lp = __halves2bfloat162(la, lb);
        l[j] = *(uint32_t*)&lp;
    }
    hi = make_uint4(h[0], h[1], h[2], h[3]);
    lo = make_uint4(l[0], l[1], l[2], l[3]);
}

// ---------------- decode GEMM via mma.sync bf16x3 ----------------
// CTA: 64 edges x 128 cols, K=832 in 26 steps of 32. 256 threads = 8 warps (2x4).
// smem stage (30720B): A_hi[64][40]bf16 @0, A_lo @5120, B_hi[128][40] @10240, B_lo @20480.
// double buffered: stage1 @30720. epilogue reuses smem: H[64][132] f32 @0, W2s @34048.
#define STAGE_SZ 30720
#define SMEM_DEC (2 * STAGE_SZ)

__global__ __launch_bounds__(256)
void decode_mma_k(const float* __restrict__ eattr,
                  const float* __restrict__ bl1, const float* __restrict__ W2,
                  const float* __restrict__ bl2,
                  float* __restrict__ out, int E) {
    extern __shared__ __align__(128) char smem[];
    uint32_t sb = smem_u32(smem);
    int tid = threadIdx.x, lane = tid & 31, wid = tid >> 5;
    int wm = wid >> 2, wn = wid & 3;           // warp grid 2(M) x 4(N)
    int e0 = blockIdx.x * 64;

    float acc[2][4][4];
#pragma unroll
    for (int a = 0; a < 2; a++)
#pragma unroll
        for (int b = 0; b < 4; b++)
#pragma unroll
            for (int c = 0; c < 4; c++) acc[a][b][c] = 0.0f;

    // A prefetch mapping: thread -> (row, 8-col group)
    int arow = tid >> 2;
    int ac8 = (tid & 3) * 8;
    int ae = e0 + arow; if (ae >= E) ae = E - 1;

    float4 aR0, aR1;
    uint4 bR[4];

#define LOAD_A(kb) do {                                                           \
    int kc = (kb) * 32;                                                           \
    const float* p = (kc < 64) ? g_nrep + (size_t)ae * 64 + kc + ac8              \
                               : eattr + (size_t)ae * 768 + (kc - 64) + ac8;      \
    aR0 = ((const float4*)p)[0]; aR1 = ((const float4*)p)[1];                     \
} while (0)

#define LOAD_B(kb) do {                                                           \
    _Pragma("unroll")                                                             \
    for (int j = 0; j < 2; j++) {                                                 \
        int idx = tid * 2 + j;                                                    \
        int n = idx >> 2, ch = idx & 3;                                           \
        size_t go = (size_t)n * 1664 + (size_t)(kb) * 64 + ch * 16;               \
        bR[j]     = *(const uint4*)((const char*)g_Bth + go);                     \
        bR[2 + j] = *(const uint4*)((const char*)g_Btl + go);                     \
    }                                                                             \
} while (0)

    LOAD_A(0); LOAD_B(0);

    for (int kb = 0; kb < NB_K; kb++) {
        int base = (kb & 1) * STAGE_SZ;
        // STS: convert A, copy B
        {
            uint4 hi, lo;
            split8(aR0, aR1, hi, lo);
            uint32_t offA = base + arow * 80 + (tid & 3) * 16;
            *(uint4*)(smem + offA) = hi;
            *(uint4*)(smem + offA + 5120) = lo;
#pragma unroll
            for (int j = 0; j < 2; j++) {
                int idx = tid * 2 + j;
                int n = idx >> 2, ch = idx & 3;
                uint32_t offB = base + 10240 + n * 80 + ch * 16;
                *(uint4*)(smem + offB) = bR[j];
                *(uint4*)(smem + offB + 10240) = bR[2 + j];
            }
        }
        __syncthreads();
        if (kb + 1 < NB_K) { LOAD_A(kb + 1); LOAD_B(kb + 1); }
        // MMA over this stage
#pragma unroll
        for (int kh = 0; kh < 2; kh++) {
            uint32_t ah[2][4], al[2][4], bh[2][4], blr[2][4];
#pragma unroll
            for (int mt = 0; mt < 2; mt++) {
                int row = wm * 32 + mt * 16 + (lane & 15);
                uint32_t off = sb + base + row * 80 + kh * 32 + (lane >> 4) * 16;
                ldm_x4(ah[mt], off);
                ldm_x4(al[mt], off + 5120);
            }
#pragma unroll
            for (int g = 0; g < 2; g++) {
                int n = wn * 32 + g * 16 + (lane & 15);
                uint32_t off = sb + base + 10240 + n * 80 + kh * 32 + (lane >> 4) * 16;
                ldm_x4(bh[g], off);
                ldm_x4(blr[g], off + 10240);
            }
#pragma unroll
            for (int mt = 0; mt < 2; mt++)
#pragma unroll
                for (int g = 0; g < 2; g++)
#pragma unroll
                    for (int p = 0; p < 2; p++) {
                        float* c = acc[mt][g * 2 + p];
                        mma_bf16(c, ah[mt], bh[g][p],  bh[g][p + 2]);
                        mma_bf16(c, ah[mt], blr[g][p], blr[g][p + 2]);
                        mma_bf16(c, al[mt], bh[g][p],  bh[g][p + 2]);
                    }
        }
    }
    __syncthreads();

    // epilogue: bias + relu -> H[64][132], and stage W2/bl2 into smem
    float* Hs = (float*)smem;
    float* W2s = (float*)(smem + 34048);       // 645 floats
#pragma unroll
    for (int mt = 0; mt < 2; mt++)
#pragma unroll
        for (int t8 = 0; t8 < 4; t8++) {
            int r0 = wm * 32 + mt * 16 + (lane >> 2);
            int cb = wn * 32 + t8 * 8 + (lane & 3) * 2;
            float b0 = __ldg(bl1 + cb), b1 = __ldg(bl1 + cb + 1);
            Hs[r0 * 132 + cb]       = fmaxf(acc[mt][t8][0] + b0, 0.0f);
            Hs[r0 * 132 + cb + 1]   = fmaxf(acc[mt][t8][1] + b1, 0.0f);
            Hs[(r0 + 8) * 132 + cb]     = fmaxf(acc[mt][t8][2] + b0, 0.0f);
            Hs[(r0 + 8) * 132 + cb + 1] = fmaxf(acc[mt][t8][3] + b1, 0.0f);
        }
    for (int i = tid; i < 645; i += 256) W2s[i] = (i < 640) ? __ldg(W2 + i) : __ldg(bl2 + i - 640);
    __syncthreads();

    if (tid < 64) {
        int e = e0 + tid;
        if (e < E) {
            float l[5];
#pragma unroll
            for (int q = 0; q < 5; q++) l[q] = W2s[640 + q];
#pragma unroll 4
            for (int k = 0; k < 128; k++) {
                float h = Hs[tid * 132 + k];
#pragma unroll
                for (int q = 0; q < 5; q++) l[q] += h * W2s[k * 5 + q];
            }
            float mx = l[0];
#pragma unroll
            for (int q = 1; q < 5; q++) mx = fmaxf(mx, l[q]);
            float s = 0.0f, ex[5];
#pragma unroll
            for (int q = 0; q < 5; q++) { ex[q] = expf(l[q] - mx); s += ex[q]; }
            float inv = 1.0f / s;
#pragma unroll
            for (int q = 0; q < 5; q++) out[e * 5 + q] = ex[q] * inv;
        }
    }
}

extern "C" void kernel_launch(void* const* d_in, const int* in_sizes, int n_in,
                              void* d_out, int out_size) {
    const float* x      = (const float*)d_in[0];
    const int*   tei    = (const int*)d_in[1];
    const int*   dei    = (const int*)d_in[2];
    const float* eattr  = (const float*)d_in[3];
    const float* Wroot1 = (const float*)d_in[4];
    const float* Wrel1  = (const float*)d_in[5];
    const float* b1     = (const float*)d_in[6];
    const float* Wroot2 = (const float*)d_in[7];
    const float* Wrel2  = (const float*)d_in[8];
    const float* b2     = (const float*)d_in[9];
    const float* W1     = (const float*)d_in[10];
    const float* bl1    = (const float*)d_in[11];
    const float* W2     = (const float*)d_in[12];
    const float* bl2    = (const float*)d_in[13];
    float* out = (float*)d_out;

    int Etr = in_sizes[1] / 2;
    int Ed  = in_sizes[2] / 2;

    static int smem_set = 0;
    if (!smem_set) {
        cudaFuncSetAttribute(decode_mma_k, cudaFuncAttributeMaxDynamicSharedMemorySize,
                             SMEM_DEC);
        smem_set = 1;
    }

    zero_k<<<(N_NODES * ZDIM + 255) / 256, 256>>>();
    prepB_k<<<(128 * 832 + 255) / 256, 256>>>(W1);
    edge1_k<<<(Etr + 255) / 256, 256>>>(tei, tei + Etr, x, Etr);
    node1_k<<<N_NODES, H1>>>(x, Wroot1, Wrel1, b1, Wroot2, Wrel2);
    {
        long threads = (long)Etr * 16;
        edge2_k<<<(int)((threads + 255) / 256), 256>>>(tei, tei + Etr, Etr);
    }
    node2_k<<<(N_NODES * ZDIM + 255) / 256, 256>>>(b2);
    {
        long threads = (long)Ed * 16;
        pair_k<<<(int)((threads + 255) / 256), 256>>>(dei, dei + Ed, Ed);
    }
    decode_mma_k<<<(Ed + 63) / 64, 256, SMEM_DEC>>>(eattr, bl1, W2, bl2, out, Ed);
}

// round 4
// speedup vs baseline: 2.2876x; 1.2173x over previous
#include <cuda_runtime.h>
#include <cuda_bf16.h>
#include <math.h>
#include <stdint.h>

#define N_NODES 100000
#define ZDIM 64
#define H1 128
#define E_DEC_MAX 200000
#define NB_K 26            // 832 / 32 K-steps for decode GEMM

// ---------------- scratch (static device arrays; no allocation) ----------------
__device__ float g_s1cnt[2 * N_NODES];           // interleaved {sum_x, count}
__device__ float g_y[N_NODES * ZDIM];            // z1 @ W_rel2
__device__ float g_r[N_NODES * ZDIM];            // z1 @ W_root2
__device__ float g_z2[N_NODES * ZDIM];           // agg2 accumulator, then z2 in-place
__device__ float g_nrep[E_DEC_MAX * ZDIM];       // z2[src]*z2[dst]
__device__ __nv_bfloat16 g_Bth[128 * 832];       // W1^T hi, n-major [128][832]
__device__ __nv_bfloat16 g_Btl[128 * 832];       // W1^T lo
__device__ __nv_bfloat16 g_W2h[128 * 128];       // [Wrel2|Wroot2]^T hi, n-major [128][128]
__device__ __nv_bfloat16 g_W2l[128 * 128];       // lo

// ---------------- PTX helpers ----------------
static __device__ __forceinline__ void red_add_v2(float* addr, float a, float b) {
    asm volatile("red.global.add.v2.f32 [%0], {%1, %2};"
                 :: "l"(addr), "f"(a), "f"(b) : "memory");
}
static __device__ __forceinline__ void red_add_v4(float* addr, float4 v) {
    asm volatile("red.global.add.v4.f32 [%0], {%1, %2, %3, %4};"
                 :: "l"(addr), "f"(v.x), "f"(v.y), "f"(v.z), "f"(v.w) : "memory");
}
static __device__ __forceinline__ uint32_t smem_u32(const void* p) {
    uint32_t a;
    asm("{ .reg .u64 t; cvta.to.shared.u64 t, %1; cvt.u32.u64 %0, t; }" : "=r"(a) : "l"(p));
    return a;
}
static __device__ __forceinline__ void ldm_x4(uint32_t* r, uint32_t addr) {
    asm volatile("ldmatrix.sync.aligned.m8n8.x4.shared.b16 {%0,%1,%2,%3}, [%4];"
                 : "=r"(r[0]), "=r"(r[1]), "=r"(r[2]), "=r"(r[3]) : "r"(addr));
}
static __device__ __forceinline__ void mma_bf16(float* c, const uint32_t* a,
                                                uint32_t b0, uint32_t b1) {
    asm volatile("mma.sync.aligned.m16n8k16.row.col.f32.bf16.bf16.f32 "
                 "{%0,%1,%2,%3}, {%4,%5,%6,%7}, {%8,%9}, {%0,%1,%2,%3};"
                 : "+f"(c[0]), "+f"(c[1]), "+f"(c[2]), "+f"(c[3])
                 : "r"(a[0]), "r"(a[1]), "r"(a[2]), "r"(a[3]), "r"(b0), "r"(b1));
}

// ---------------- zero scratch ----------------
__global__ void zero_k() {
    int i = blockIdx.x * blockDim.x + threadIdx.x;
    if (i < 2 * N_NODES) g_s1cnt[i] = 0.0f;
    if (i < N_NODES * ZDIM) g_z2[i] = 0.0f;
}

// ---------------- layer-1 edge pass ----------------
__global__ void edge1_k(const int* __restrict__ src, const int* __restrict__ dst,
                        const float* __restrict__ x, int E) {
    int e = blockIdx.x * blockDim.x + threadIdx.x;
    if (e >= E) return;
    int s = src[e], d = dst[e];
    red_add_v2(&g_s1cnt[2 * d], x[s], 1.0f);
}

// ---------------- layer-2 edge scatter ----------------
__global__ void edge2_k(const int* __restrict__ src, const int* __restrict__ dst, int E) {
    int idx = blockIdx.x * blockDim.x + threadIdx.x;
    int e = idx >> 4;
    if (e >= E) return;
    int g = idx & 15;
    int s = src[e], d = dst[e];
    float4 v = ((const float4*)g_y)[s * 16 + g];
    red_add_v4(&g_z2[d * ZDIM + g * 4], v);
}

// ---------------- z2 = relu(r + agg2/cnt + b2) ----------------
__global__ void node2_k(const float* __restrict__ b2) {
    int i = blockIdx.x * blockDim.x + threadIdx.x;
    if (i >= N_NODES * ZDIM) return;
    int n = i >> 6, c = i & 63;
    float cnt = g_s1cnt[2 * n + 1];
    float v = g_r[i] + g_z2[i] / fmaxf(cnt, 1.0f) + b2[c];
    g_z2[i] = fmaxf(v, 0.0f);
}

// ---------------- decode pair gather ----------------
__global__ void pair_k(const int* __restrict__ src, const int* __restrict__ dst, int E) {
    int idx = blockIdx.x * blockDim.x + threadIdx.x;
    int e = idx >> 4;
    if (e >= E) return;
    int g = idx & 15;
    int s = src[e], d = dst[e];
    float4 a = ((const float4*)g_z2)[s * 16 + g];
    float4 b = ((const float4*)g_z2)[d * 16 + g];
    float4 o;
    o.x = a.x * b.x; o.y = a.y * b.y; o.z = a.z * b.z; o.w = a.w * b.w;
    ((float4*)g_nrep)[e * 16 + g] = o;
}

// ---------------- W1^T bf16 hi/lo split (n-major [128][832]) ----------------
__global__ void prepB_k(const float* __restrict__ W1) {
    int i = blockIdx.x * blockDim.x + threadIdx.x;
    if (i >= 128 * 832) return;
    int n = i / 832, k = i % 832;
    float w = W1[k * 128 + n];
    __nv_bfloat16 hi = __float2bfloat16(w);
    __nv_bfloat16 lo = __float2bfloat16(w - __bfloat162float(hi));
    g_Bth[i] = hi;
    g_Btl[i] = lo;
}

// ---------------- [Wrel2|Wroot2] bf16 hi/lo split (n-major [128][128]) ----------------
__global__ void prepW2_k(const float* __restrict__ Wrel2, const float* __restrict__ Wroot2) {
    int i = blockIdx.x * blockDim.x + threadIdx.x;
    if (i >= 128 * 128) return;
    int n = i >> 7, k = i & 127;
    float w = (n < 64) ? Wrel2[k * 64 + n] : Wroot2[k * 64 + (n - 64)];
    __nv_bfloat16 hi = __float2bfloat16(w);
    __nv_bfloat16 lo = __float2bfloat16(w - __bfloat162float(hi));
    g_W2h[i] = hi;
    g_W2l[i] = lo;
}

// ---------------- split 8 fp32 -> bf16 hi/lo uint4 ----------------
static __device__ __forceinline__ void split8(float4 v0, float4 v1, uint4& hi, uint4& lo) {
    float f[8] = {v0.x, v0.y, v0.z, v0.w, v1.x, v1.y, v1.z, v1.w};
    uint32_t h[4], l[4];
#pragma unroll
    for (int j = 0; j < 4; j++) {
        __nv_bfloat16 a = __float2bfloat16(f[2 * j]);
        __nv_bfloat16 b = __float2bfloat16(f[2 * j + 1]);
        __nv_bfloat162 hp = __halves2bfloat162(a, b);
        h[j] = *(uint32_t*)&hp;
        __nv_bfloat16 la = __float2bfloat16(f[2 * j]     - __bfloat162float(a));
        __nv_bfloat16 lb = __float2bfloat16(f[2 * j + 1] - __bfloat162float(b));
        __nv_bfloat162 lp = __halves2bfloat162(la, lb);
        l[j] = *(uint32_t*)&lp;
    }
    hi = make_uint4(h[0], h[1], h[2], h[3]);
    lo = make_uint4(l[0], l[1], l[2], l[3]);
}

// ======== node1 via mma: z1 = relu(x*Wroot1 + m*Wrel1 + b1); [y|r] = z1 @ [Wrel2|Wroot2]
// CTA = 64 nodes x 128 outs, K=128 in 4 chunks of 32. Same staging layout as decode.
// smem: stage 30720B @0  |  z1 fp32 [64][128] @30720 (32768B)  => 63488B
#define N1_SMEM (30720 + 32768)
__global__ __launch_bounds__(256)
void node1_mma_k(const float* __restrict__ x,
                 const float* __restrict__ Wroot1, const float* __restrict__ Wrel1,
                 const float* __restrict__ b1) {
    extern __shared__ __align__(128) char smem[];
    uint32_t sb = smem_u32(smem);
    float* z1s = (float*)(smem + 30720);
    int tid = threadIdx.x, lane = tid & 31, wid = tid >> 5;
    int wm = wid >> 2, wn = wid & 3;
    int n0 = blockIdx.x * 64;

    // ---- compute z1 into smem ----
    {
        int nl = tid >> 2;                 // 0..63
        int q  = tid & 3;
        int node = n0 + nl; if (node >= N_NODES) node = N_NODES - 1;
        float xi = x[node];
        float2 sc = ((const float2*)g_s1cnt)[node];
        float m = sc.x / fmaxf(sc.y, 1.0f);
#pragma unroll
        for (int j = 0; j < 32; j++) {
            int c = q * 32 + j;
            z1s[nl * 128 + c] =
                fmaxf(xi * __ldg(Wroot1 + c) + m * __ldg(Wrel1 + c) + __ldg(b1 + c), 0.0f);
        }
    }
    __syncthreads();

    float acc[2][4][4];
#pragma unroll
    for (int a = 0; a < 2; a++)
#pragma unroll
        for (int b = 0; b < 4; b++)
#pragma unroll
            for (int c = 0; c < 4; c++) acc[a][b][c] = 0.0f;

    int arow = tid >> 2;
    int a4 = (tid & 3);

    for (int kb = 0; kb < 4; kb++) {
        // A: convert z1 chunk
        {
            float4 a0 = *(float4*)&z1s[arow * 128 + kb * 32 + a4 * 8];
            float4 a1 = *(float4*)&z1s[arow * 128 + kb * 32 + a4 * 8 + 4];
            uint4 hi, lo;
            split8(a0, a1, hi, lo);
            uint32_t offA = arow * 80 + a4 * 16;
            *(uint4*)(smem + offA) = hi;
            *(uint4*)(smem + offA + 5120) = lo;
        }
        // B: copy hi/lo chunk (L2-resident)
#pragma unroll
        for (int j = 0; j < 2; j++) {
            int idx = tid * 2 + j;
            int n = idx >> 2, ch = idx & 3;
            size_t go = (size_t)n * 256 + (size_t)kb * 64 + ch * 16;
            uint32_t offB = 10240 + n * 80 + ch * 16;
            *(uint4*)(smem + offB) = *(const uint4*)((const char*)g_W2h + go);
            *(uint4*)(smem + offB + 10240) = *(const uint4*)((const char*)g_W2l + go);
        }
        __syncthreads();
#pragma unroll
        for (int kh = 0; kh < 2; kh++) {
            uint32_t ah[2][4], al[2][4], bh[2][4], blr[2][4];
#pragma unroll
            for (int mt = 0; mt < 2; mt++) {
                int row = wm * 32 + mt * 16 + (lane & 15);
                uint32_t off = sb + row * 80 + kh * 32 + (lane >> 4) * 16;
                ldm_x4(ah[mt], off);
                ldm_x4(al[mt], off + 5120);
            }
#pragma unroll
            for (int g = 0; g < 2; g++) {
                int n = wn * 32 + g * 16 + (lane & 15);
                uint32_t off = sb + 10240 + n * 80 + kh * 32 + (lane >> 4) * 16;
                ldm_x4(bh[g], off);
                ldm_x4(blr[g], off + 10240);
            }
#pragma unroll
            for (int mt = 0; mt < 2; mt++)
#pragma unroll
                for (int g = 0; g < 2; g++)
#pragma unroll
                    for (int p = 0; p < 2; p++) {
                        float* c = acc[mt][g * 2 + p];
                        mma_bf16(c, ah[mt], bh[g][p],  bh[g][p + 2]);
                        mma_bf16(c, ah[mt], blr[g][p], blr[g][p + 2]);
                        mma_bf16(c, al[mt], bh[g][p],  bh[g][p + 2]);
                    }
        }
        __syncthreads();
    }

    // ---- writeout: cols [0,64) -> g_y, [64,128) -> g_r ----
#pragma unroll
    for (int mt = 0; mt < 2; mt++)
#pragma unroll
        for (int t8 = 0; t8 < 4; t8++) {
            int r0 = wm * 32 + mt * 16 + (lane >> 2);
            int cb = wn * 32 + t8 * 8 + (lane & 3) * 2;
            float* dst = (cb < 64) ? g_y : g_r;
            int c = cb & 63;
#pragma unroll
            for (int half = 0; half < 2; half++) {
                int node = n0 + r0 + half * 8;
                if (node < N_NODES) {
                    dst[node * 64 + c]     = acc[mt][t8][half * 2];
                    dst[node * 64 + c + 1] = acc[mt][t8][half * 2 + 1];
                }
            }
        }
}

// ---------------- decode GEMM via mma.sync bf16x3 (unchanged from R3) ----------------
#define STAGE_SZ 30720
#define SMEM_DEC (2 * STAGE_SZ)

__global__ __launch_bounds__(256)
void decode_mma_k(const float* __restrict__ eattr,
                  const float* __restrict__ bl1, const float* __restrict__ W2,
                  const float* __restrict__ bl2,
                  float* __restrict__ out, int E) {
    extern __shared__ __align__(128) char smem[];
    uint32_t sb = smem_u32(smem);
    int tid = threadIdx.x, lane = tid & 31, wid = tid >> 5;
    int wm = wid >> 2, wn = wid & 3;
    int e0 = blockIdx.x * 64;

    float acc[2][4][4];
#pragma unroll
    for (int a = 0; a < 2; a++)
#pragma unroll
        for (int b = 0; b < 4; b++)
#pragma unroll
            for (int c = 0; c < 4; c++) acc[a][b][c] = 0.0f;

    int arow = tid >> 2;
    int ac8 = (tid & 3) * 8;
    int ae = e0 + arow; if (ae >= E) ae = E - 1;

    float4 aR0, aR1;
    uint4 bR[4];

#define LOAD_A(kb) do {                                                           \
    int kc = (kb) * 32;                                                           \
    const float* p = (kc < 64) ? g_nrep + (size_t)ae * 64 + kc + ac8              \
                               : eattr + (size_t)ae * 768 + (kc - 64) + ac8;      \
    aR0 = ((const float4*)p)[0]; aR1 = ((const float4*)p)[1];                     \
} while (0)

#define LOAD_B(kb) do {                                                           \
    _Pragma("unroll")                                                             \
    for (int j = 0; j < 2; j++) {                                                 \
        int idx = tid * 2 + j;                                                    \
        int n = idx >> 2, ch = idx & 3;                                           \
        size_t go = (size_t)n * 1664 + (size_t)(kb) * 64 + ch * 16;               \
        bR[j]     = *(const uint4*)((const char*)g_Bth + go);                     \
        bR[2 + j] = *(const uint4*)((const char*)g_Btl + go);                     \
    }                                                                             \
} while (0)

    LOAD_A(0); LOAD_B(0);

    for (int kb = 0; kb < NB_K; kb++) {
        int base = (kb & 1) * STAGE_SZ;
        {
            uint4 hi, lo;
            split8(aR0, aR1, hi, lo);
            uint32_t offA = base + arow * 80 + (tid & 3) * 16;
            *(uint4*)(smem + offA) = hi;
            *(uint4*)(smem + offA + 5120) = lo;
#pragma unroll
            for (int j = 0; j < 2; j++) {
                int idx = tid * 2 + j;
                int n = idx >> 2, ch = idx & 3;
                uint32_t offB = base + 10240 + n * 80 + ch * 16;
                *(uint4*)(smem + offB) = bR[j];
                *(uint4*)(smem + offB + 10240) = bR[2 + j];
            }
        }
        __syncthreads();
        if (kb + 1 < NB_K) { LOAD_A(kb + 1); LOAD_B(kb + 1); }
#pragma unroll
        for (int kh = 0; kh < 2; kh++) {
            uint32_t ah[2][4], al[2][4], bh[2][4], blr[2][4];
#pragma unroll
            for (int mt = 0; mt < 2; mt++) {
                int row = wm * 32 + mt * 16 + (lane & 15);
                uint32_t off = sb + base + row * 80 + kh * 32 + (lane >> 4) * 16;
                ldm_x4(ah[mt], off);
                ldm_x4(al[mt], off + 5120);
            }
#pragma unroll
            for (int g = 0; g < 2; g++) {
                int n = wn * 32 + g * 16 + (lane & 15);
                uint32_t off = sb + base + 10240 + n * 80 + kh * 32 + (lane >> 4) * 16;
                ldm_x4(bh[g], off);
                ldm_x4(blr[g], off + 10240);
            }
#pragma unroll
            for (int mt = 0; mt < 2; mt++)
#pragma unroll
                for (int g = 0; g < 2; g++)
#pragma unroll
                    for (int p = 0; p < 2; p++) {
                        float* c = acc[mt][g * 2 + p];
                        mma_bf16(c, ah[mt], bh[g][p],  bh[g][p + 2]);
                        mma_bf16(c, ah[mt], blr[g][p], blr[g][p + 2]);
                        mma_bf16(c, al[mt], bh[g][p],  bh[g][p + 2]);
                    }
        }
    }
    __syncthreads();

    float* Hs = (float*)smem;
    float* W2s = (float*)(smem + 34048);
#pragma unroll
    for (int mt = 0; mt < 2; mt++)
#pragma unroll
        for (int t8 = 0; t8 < 4; t8++) {
            int r0 = wm * 32 + mt * 16 + (lane >> 2);
            int cb = wn * 32 + t8 * 8 + (lane & 3) * 2;
            float b0 = __ldg(bl1 + cb), b1 = __ldg(bl1 + cb + 1);
            Hs[r0 * 132 + cb]       = fmaxf(acc[mt][t8][0] + b0, 0.0f);
            Hs[r0 * 132 + cb + 1]   = fmaxf(acc[mt][t8][1] + b1, 0.0f);
            Hs[(r0 + 8) * 132 + cb]     = fmaxf(acc[mt][t8][2] + b0, 0.0f);
            Hs[(r0 + 8) * 132 + cb + 1] = fmaxf(acc[mt][t8][3] + b1, 0.0f);
        }
    for (int i = tid; i < 645; i += 256) W2s[i] = (i < 640) ? __ldg(W2 + i) : __ldg(bl2 + i - 640);
    __syncthreads();

    if (tid < 64) {
        int e = e0 + tid;
        if (e < E) {
            float l[5];
#pragma unroll
            for (int q = 0; q < 5; q++) l[q] = W2s[640 + q];
#pragma unroll 4
            for (int k = 0; k < 128; k++) {
                float h = Hs[tid * 132 + k];
#pragma unroll
                for (int q = 0; q < 5; q++) l[q] += h * W2s[k * 5 + q];
            }
            float mx = l[0];
#pragma unroll
            for (int q = 1; q < 5; q++) mx = fmaxf(mx, l[q]);
            float s = 0.0f, ex[5];
#pragma unroll
            for (int q = 0; q < 5; q++) { ex[q] = expf(l[q] - mx); s += ex[q]; }
            float inv = 1.0f / s;
#pragma unroll
            for (int q = 0; q < 5; q++) out[e * 5 + q] = ex[q] * inv;
        }
    }
}

extern "C" void kernel_launch(void* const* d_in, const int* in_sizes, int n_in,
                              void* d_out, int out_size) {
    const float* x      = (const float*)d_in[0];
    const int*   tei    = (const int*)d_in[1];
    const int*   dei    = (const int*)d_in[2];
    const float* eattr  = (const float*)d_in[3];
    const float* Wroot1 = (const float*)d_in[4];
    const float* Wrel1  = (const float*)d_in[5];
    const float* b1     = (const float*)d_in[6];
    const float* Wroot2 = (const float*)d_in[7];
    const float* Wrel2  = (const float*)d_in[8];
    const float* b2     = (const float*)d_in[9];
    const float* W1     = (const float*)d_in[10];
    const float* bl1    = (const float*)d_in[11];
    const float* W2     = (const float*)d_in[12];
    const float* bl2    = (const float*)d_in[13];
    float* out = (float*)d_out;

    int Etr = in_sizes[1] / 2;
    int Ed  = in_sizes[2] / 2;

    static int smem_set = 0;
    if (!smem_set) {
        cudaFuncSetAttribute(decode_mma_k, cudaFuncAttributeMaxDynamicSharedMemorySize,
                             SMEM_DEC);
        cudaFuncSetAttribute(node1_mma_k, cudaFuncAttributeMaxDynamicSharedMemorySize,
                             N1_SMEM);
        smem_set = 1;
    }

    zero_k<<<(N_NODES * ZDIM + 255) / 256, 256>>>();
    prepB_k<<<(128 * 832 + 255) / 256, 256>>>(W1);
    prepW2_k<<<(128 * 128 + 255) / 256, 256>>>(Wrel2, Wroot2);
    edge1_k<<<(Etr + 255) / 256, 256>>>(tei, tei + Etr, x, Etr);
    node1_mma_k<<<(N_NODES + 63) / 64, 256, N1_SMEM>>>(x, Wroot1, Wrel1, b1);
    {
        long threads = (long)Etr * 16;
        edge2_k<<<(int)((threads + 255) / 256), 256>>>(tei, tei + Etr, Etr);
    }
    node2_k<<<(N_NODES * ZDIM + 255) / 256, 256>>>(b2);
    {
        long threads = (long)Ed * 16;
        pair_k<<<(int)((threads + 255) / 256), 256>>>(dei, dei + Ed, Ed);
    }
    decode_mma_k<<<(Ed + 63) / 64, 256, SMEM_DEC>>>(eattr, bl1, W2, bl2, out, Ed);
}

// round 5
// speedup vs baseline: 2.2984x; 1.0047x over previous
#include <cuda_runtime.h>
#include <cuda_bf16.h>
#include <math.h>
#include <stdint.h>

#define N_NODES 100000
#define ZDIM 64
#define H1 128
#define E_DEC_MAX 200000
#define NB_K 26            // 832 / 32 K-steps for decode GEMM

// ---------------- scratch ----------------
__device__ float g_s1cnt[2 * N_NODES];
__device__ float g_y[N_NODES * ZDIM];
__device__ float g_r[N_NODES * ZDIM];
__device__ float g_z2[N_NODES * ZDIM];
__device__ float g_nrep[E_DEC_MAX * ZDIM];
__device__ __nv_bfloat16 g_Bth[128 * 832];       // W1^T hi, n-major
__device__ __nv_bfloat16 g_Btl[128 * 832];       // W1^T lo
__device__ __nv_bfloat16 g_W2h[128 * 128];       // [Wrel2|Wroot2]^T hi, n-major
__device__ __nv_bfloat16 g_W2l[128 * 128];

// ---------------- PTX helpers ----------------
static __device__ __forceinline__ void red_add_v2(float* addr, float a, float b) {
    asm volatile("red.global.add.v2.f32 [%0], {%1, %2};"
                 :: "l"(addr), "f"(a), "f"(b) : "memory");
}
static __device__ __forceinline__ void red_add_v4(float* addr, float4 v) {
    asm volatile("red.global.add.v4.f32 [%0], {%1, %2, %3, %4};"
                 :: "l"(addr), "f"(v.x), "f"(v.y), "f"(v.z), "f"(v.w) : "memory");
}
static __device__ __forceinline__ uint32_t smem_u32(const void* p) {
    uint32_t a;
    asm("{ .reg .u64 t; cvta.to.shared.u64 t, %1; cvt.u32.u64 %0, t; }" : "=r"(a) : "l"(p));
    return a;
}
static __device__ __forceinline__ void ldm_x4(uint32_t* r, uint32_t addr) {
    asm volatile("ldmatrix.sync.aligned.m8n8.x4.shared.b16 {%0,%1,%2,%3}, [%4];"
                 : "=r"(r[0]), "=r"(r[1]), "=r"(r[2]), "=r"(r[3]) : "r"(addr));
}
static __device__ __forceinline__ void mma_bf16(float* c, const uint32_t* a,
                                                uint32_t b0, uint32_t b1) {
    asm volatile("mma.sync.aligned.m16n8k16.row.col.f32.bf16.bf16.f32 "
                 "{%0,%1,%2,%3}, {%4,%5,%6,%7}, {%8,%9}, {%0,%1,%2,%3};"
                 : "+f"(c[0]), "+f"(c[1]), "+f"(c[2]), "+f"(c[3])
                 : "r"(a[0]), "r"(a[1]), "r"(a[2]), "r"(a[3]), "r"(b0), "r"(b1));
}
static __device__ __forceinline__ void cp_async16(uint32_t dst, const void* src) {
    asm volatile("cp.async.cg.shared.global [%0], [%1], 16;" :: "r"(dst), "l"(src));
}
static __device__ __forceinline__ void cp_commit() {
    asm volatile("cp.async.commit_group;");
}
static __device__ __forceinline__ void cp_wait0() {
    asm volatile("cp.async.wait_group 0;" ::: "memory");
}

// ---------------- zero scratch ----------------
__global__ void zero_k() {
    int i = blockIdx.x * blockDim.x + threadIdx.x;
    if (i < 2 * N_NODES) g_s1cnt[i] = 0.0f;
    if (i < N_NODES * ZDIM) g_z2[i] = 0.0f;
}

// ---------------- layer-1 edge pass ----------------
__global__ void edge1_k(const int* __restrict__ src, const int* __restrict__ dst,
                        const float* __restrict__ x, int E) {
    int e = blockIdx.x * blockDim.x + threadIdx.x;
    if (e >= E) return;
    int s = src[e], d = dst[e];
    red_add_v2(&g_s1cnt[2 * d], x[s], 1.0f);
}

// ---------------- layer-2 edge scatter ----------------
__global__ void edge2_k(const int* __restrict__ src, const int* __restrict__ dst, int E) {
    int idx = blockIdx.x * blockDim.x + threadIdx.x;
    int e = idx >> 4;
    if (e >= E) return;
    int g = idx & 15;
    int s = src[e], d = dst[e];
    float4 v = ((const float4*)g_y)[s * 16 + g];
    red_add_v4(&g_z2[d * ZDIM + g * 4], v);
}

// ---------------- z2 = relu(r + agg2/cnt + b2) ----------------
__global__ void node2_k(const float* __restrict__ b2) {
    int i = blockIdx.x * blockDim.x + threadIdx.x;
    if (i >= N_NODES * ZDIM) return;
    int n = i >> 6, c = i & 63;
    float cnt = g_s1cnt[2 * n + 1];
    float v = g_r[i] + g_z2[i] / fmaxf(cnt, 1.0f) + b2[c];
    g_z2[i] = fmaxf(v, 0.0f);
}

// ---------------- decode pair gather ----------------
__global__ void pair_k(const int* __restrict__ src, const int* __restrict__ dst, int E) {
    int idx = blockIdx.x * blockDim.x + threadIdx.x;
    int e = idx >> 4;
    if (e >= E) return;
    int g = idx & 15;
    int s = src[e], d = dst[e];
    float4 a = ((const float4*)g_z2)[s * 16 + g];
    float4 b = ((const float4*)g_z2)[d * 16 + g];
    float4 o;
    o.x = a.x * b.x; o.y = a.y * b.y; o.z = a.z * b.z; o.w = a.w * b.w;
    ((float4*)g_nrep)[e * 16 + g] = o;
}

// ---------------- W1^T bf16 hi/lo split ----------------
__global__ void prepB_k(const float* __restrict__ W1) {
    int i = blockIdx.x * blockDim.x + threadIdx.x;
    if (i >= 128 * 832) return;
    int n = i / 832, k = i % 832;
    float w = W1[k * 128 + n];
    __nv_bfloat16 hi = __float2bfloat16(w);
    __nv_bfloat16 lo = __float2bfloat16(w - __bfloat162float(hi));
    g_Bth[i] = hi;
    g_Btl[i] = lo;
}

// ---------------- [Wrel2|Wroot2] split ----------------
__global__ void prepW2_k(const float* __restrict__ Wrel2, const float* __restrict__ Wroot2) {
    int i = blockIdx.x * blockDim.x + threadIdx.x;
    if (i >= 128 * 128) return;
    int n = i >> 7, k = i & 127;
    float w = (n < 64) ? Wrel2[k * 64 + n] : Wroot2[k * 64 + (n - 64)];
    __nv_bfloat16 hi = __float2bfloat16(w);
    __nv_bfloat16 lo = __float2bfloat16(w - __bfloat162float(hi));
    g_W2h[i] = hi;
    g_W2l[i] = lo;
}

// ---------------- split 8 fp32 -> bf16 hi/lo ----------------
static __device__ __forceinline__ void split8(float4 v0, float4 v1, uint4& hi, uint4& lo) {
    float f[8] = {v0.x, v0.y, v0.z, v0.w, v1.x, v1.y, v1.z, v1.w};
    uint32_t h[4], l[4];
#pragma unroll
    for (int j = 0; j < 4; j++) {
        __nv_bfloat16 a = __float2bfloat16(f[2 * j]);
        __nv_bfloat16 b = __float2bfloat16(f[2 * j + 1]);
        __nv_bfloat162 hp = __halves2bfloat162(a, b);
        h[j] = *(uint32_t*)&hp;
        __nv_bfloat16 la = __float2bfloat16(f[2 * j]     - __bfloat162float(a));
        __nv_bfloat16 lb = __float2bfloat16(f[2 * j + 1] - __bfloat162float(b));
        __nv_bfloat162 lp = __halves2bfloat162(la, lb);
        l[j] = *(uint32_t*)&lp;
    }
    hi = make_uint4(h[0], h[1], h[2], h[3]);
    lo = make_uint4(l[0], l[1], l[2], l[3]);
}

// ======== node1 via mma (unchanged from R4) ========
#define N1_SMEM (30720 + 32768)
__global__ __launch_bounds__(256)
void node1_mma_k(const float* __restrict__ x,
                 const float* __restrict__ Wroot1, const float* __restrict__ Wrel1,
                 const float* __restrict__ b1) {
    extern __shared__ __align__(128) char smem[];
    uint32_t sb = smem_u32(smem);
    float* z1s = (float*)(smem + 30720);
    int tid = threadIdx.x, lane = tid & 31, wid = tid >> 5;
    int wm = wid >> 2, wn = wid & 3;
    int n0 = blockIdx.x * 64;

    {
        int nl = tid >> 2;
        int q  = tid & 3;
        int node = n0 + nl; if (node >= N_NODES) node = N_NODES - 1;
        float xi = x[node];
        float2 sc = ((const float2*)g_s1cnt)[node];
        float m = sc.x / fmaxf(sc.y, 1.0f);
#pragma unroll
        for (int j = 0; j < 32; j++) {
            int c = q * 32 + j;
            z1s[nl * 128 + c] =
                fmaxf(xi * __ldg(Wroot1 + c) + m * __ldg(Wrel1 + c) + __ldg(b1 + c), 0.0f);
        }
    }
    __syncthreads();

    float acc[2][4][4];
#pragma unroll
    for (int a = 0; a < 2; a++)
#pragma unroll
        for (int b = 0; b < 4; b++)
#pragma unroll
            for (int c = 0; c < 4; c++) acc[a][b][c] = 0.0f;

    int arow = tid >> 2;
    int a4 = (tid & 3);

    for (int kb = 0; kb < 4; kb++) {
        {
            float4 a0 = *(float4*)&z1s[arow * 128 + kb * 32 + a4 * 8];
            float4 a1 = *(float4*)&z1s[arow * 128 + kb * 32 + a4 * 8 + 4];
            uint4 hi, lo;
            split8(a0, a1, hi, lo);
            uint32_t offA = arow * 80 + a4 * 16;
            *(uint4*)(smem + offA) = hi;
            *(uint4*)(smem + offA + 5120) = lo;
        }
#pragma unroll
        for (int j = 0; j < 2; j++) {
            int idx = tid * 2 + j;
            int n = idx >> 2, ch = idx & 3;
            size_t go = (size_t)n * 256 + (size_t)kb * 64 + ch * 16;
            uint32_t offB = 10240 + n * 80 + ch * 16;
            *(uint4*)(smem + offB) = *(const uint4*)((const char*)g_W2h + go);
            *(uint4*)(smem + offB + 10240) = *(const uint4*)((const char*)g_W2l + go);
        }
        __syncthreads();
#pragma unroll
        for (int kh = 0; kh < 2; kh++) {
            uint32_t ah[2][4], al[2][4], bh[2][4], blr[2][4];
#pragma unroll
            for (int mt = 0; mt < 2; mt++) {
                int row = wm * 32 + mt * 16 + (lane & 15);
                uint32_t off = sb + row * 80 + kh * 32 + (lane >> 4) * 16;
                ldm_x4(ah[mt], off);
                ldm_x4(al[mt], off + 5120);
            }
#pragma unroll
            for (int g = 0; g < 2; g++) {
                int n = wn * 32 + g * 16 + (lane & 15);
                uint32_t off = sb + 10240 + n * 80 + kh * 32 + (lane >> 4) * 16;
                ldm_x4(bh[g], off);
                ldm_x4(blr[g], off + 10240);
            }
#pragma unroll
            for (int mt = 0; mt < 2; mt++)
#pragma unroll
                for (int g = 0; g < 2; g++)
#pragma unroll
                    for (int p = 0; p < 2; p++) {
                        float* c = acc[mt][g * 2 + p];
                        mma_bf16(c, ah[mt], bh[g][p],  bh[g][p + 2]);
                        mma_bf16(c, ah[mt], blr[g][p], blr[g][p + 2]);
                        mma_bf16(c, al[mt], bh[g][p],  bh[g][p + 2]);
                    }
        }
        __syncthreads();
    }

#pragma unroll
    for (int mt = 0; mt < 2; mt++)
#pragma unroll
        for (int t8 = 0; t8 < 4; t8++) {
            int r0 = wm * 32 + mt * 16 + (lane >> 2);
            int cb = wn * 32 + t8 * 8 + (lane & 3) * 2;
            float* dst = (cb < 64) ? g_y : g_r;
            int c = cb & 63;
#pragma unroll
            for (int half = 0; half < 2; half++) {
                int node = n0 + r0 + half * 8;
                if (node < N_NODES) {
                    dst[node * 64 + c]     = acc[mt][t8][half * 2];
                    dst[node * 64 + c + 1] = acc[mt][t8][half * 2 + 1];
                }
            }
        }
}

// ======== decode GEMM v2: CTA 128x128, cp.async B, bf16x3 ========
// stage (40960B): A_hi[128][80] @0, A_lo @10240, B_hi[128][80] @20480, B_lo @30720
// double buffered: 81920B. epilogue: H[128][132] f32 @0 (67584), W2s @67584.
#define STAGE2_SZ 40960
#define SMEM_DEC (2 * STAGE2_SZ)

__global__ __launch_bounds__(256)
void decode_mma_k(const float* __restrict__ eattr,
                  const float* __restrict__ bl1, const float* __restrict__ W2,
                  const float* __restrict__ bl2,
                  float* __restrict__ out, int E) {
    extern __shared__ __align__(128) char smem[];
    uint32_t sb = smem_u32(smem);
    int tid = threadIdx.x, lane = tid & 31, wid = tid >> 5;
    int wm = wid >> 1, wn = wid & 1;           // warp grid 4(M) x 2(N), warp tile 32x64
    int e0 = blockIdx.x * 128;

    float acc[2][8][4];
#pragma unroll
    for (int a = 0; a < 2; a++)
#pragma unroll
        for (int b = 0; b < 8; b++)
#pragma unroll
            for (int c = 0; c < 4; c++) acc[a][b][c] = 0.0f;

    // A mapping: thread -> (row, k-half of 16)
    int arow = tid >> 1;
    int ahalf = tid & 1;
    int ae = e0 + arow; if (ae >= E) ae = E - 1;

    // B mapping for cp.async: thread -> (n-row, k-half)
    int bn = tid >> 1;
    int bhalf = tid & 1;

    float4 aR[4];

#define LOAD_A2(kb) do {                                                          \
    int kc = (kb) * 32 + ahalf * 16;                                              \
    const float* p = (kc < 64) ? g_nrep + (size_t)ae * 64 + kc                    \
                               : eattr + (size_t)ae * 768 + (kc - 64);            \
    aR[0] = ((const float4*)p)[0]; aR[1] = ((const float4*)p)[1];                 \
    aR[2] = ((const float4*)p)[2]; aR[3] = ((const float4*)p)[3];                 \
} while (0)

#define ISSUE_B2(kb, stagebase) do {                                              \
    const char* sh = (const char*)g_Bth + (size_t)bn * 1664 + (size_t)(kb) * 64 + bhalf * 32; \
    const char* sl = (const char*)g_Btl + (size_t)bn * 1664 + (size_t)(kb) * 64 + bhalf * 32; \
    uint32_t dh = sb + (stagebase) + 20480 + bn * 80 + bhalf * 32;                \
    cp_async16(dh, sh); cp_async16(dh + 16, sh + 16);                             \
    cp_async16(dh + 10240, sl); cp_async16(dh + 10240 + 16, sl + 16);             \
    cp_commit();                                                                  \
} while (0)

    ISSUE_B2(0, 0);
    LOAD_A2(0);

    for (int kb = 0; kb < NB_K; kb++) {
        int base = (kb & 1) * STAGE2_SZ;
        // STS A (convert)
        {
            uint4 hi0, lo0, hi1, lo1;
            split8(aR[0], aR[1], hi0, lo0);
            split8(aR[2], aR[3], hi1, lo1);
            uint32_t offA = base + arow * 80 + ahalf * 32;
            *(uint4*)(smem + offA)          = hi0;
            *(uint4*)(smem + offA + 16)     = hi1;
            *(uint4*)(smem + offA + 10240)      = lo0;
            *(uint4*)(smem + offA + 10240 + 16) = lo1;
        }
        cp_wait0();
        __syncthreads();
        if (kb + 1 < NB_K) {
            ISSUE_B2(kb + 1, (kb & 1) ? 0 : STAGE2_SZ);
            LOAD_A2(kb + 1);
        }
#pragma unroll
        for (int kh = 0; kh < 2; kh++) {
            uint32_t ah[2][4], al[2][4], bh[4][4], bl[4][4];
#pragma unroll
            for (int mt = 0; mt < 2; mt++) {
                int row = wm * 32 + mt * 16 + (lane & 15);
                uint32_t off = sb + base + row * 80 + kh * 32 + (lane >> 4) * 16;
                ldm_x4(ah[mt], off);
                ldm_x4(al[mt], off + 10240);
            }
#pragma unroll
            for (int g = 0; g < 4; g++) {
                int n = wn * 64 + g * 16 + (lane & 15);
                uint32_t off = sb + base + 20480 + n * 80 + kh * 32 + (lane >> 4) * 16;
                ldm_x4(bh[g], off);
                ldm_x4(bl[g], off + 10240);
            }
#pragma unroll
            for (int mt = 0; mt < 2; mt++)
#pragma unroll
                for (int g = 0; g < 4; g++)
#pragma unroll
                    for (int p = 0; p < 2; p++) {
                        float* c = acc[mt][g * 2 + p];
                        mma_bf16(c, ah[mt], bh[g][p], bh[g][p + 2]);
                        mma_bf16(c, ah[mt], bl[g][p], bl[g][p + 2]);
                        mma_bf16(c, al[mt], bh[g][p], bh[g][p + 2]);
                    }
        }
        __syncthreads();
    }

    // epilogue
    float* Hs = (float*)smem;
    float* W2s = (float*)(smem + 67584);       // 645 floats
#pragma unroll
    for (int mt = 0; mt < 2; mt++)
#pragma unroll
        for (int g = 0; g < 4; g++)
#pragma unroll
            for (int p = 0; p < 2; p++) {
                int r0 = wm * 32 + mt * 16 + (lane >> 2);
                int cb = wn * 64 + g * 16 + p * 8 + (lane & 3) * 2;
                float b0 = __ldg(bl1 + cb), b1 = __ldg(bl1 + cb + 1);
                float* c = acc[mt][g * 2 + p];
                Hs[r0 * 132 + cb]           = fmaxf(c[0] + b0, 0.0f);
                Hs[r0 * 132 + cb + 1]       = fmaxf(c[1] + b1, 0.0f);
                Hs[(r0 + 8) * 132 + cb]     = fmaxf(c[2] + b0, 0.0f);
                Hs[(r0 + 8) * 132 + cb + 1] = fmaxf(c[3] + b1, 0.0f);
            }
    for (int i = tid; i < 645; i += 256) W2s[i] = (i < 640) ? __ldg(W2 + i) : __ldg(bl2 + i - 640);
    __syncthreads();

    if (tid < 128) {
        int e = e0 + tid;
        if (e < E) {
            float l[5];
#pragma unroll
            for (int q = 0; q < 5; q++) l[q] = W2s[640 + q];
#pragma unroll 4
            for (int k = 0; k < 128; k++) {
                float h = Hs[tid * 132 + k];
#pragma unroll
                for (int q = 0; q < 5; q++) l[q] += h * W2s[k * 5 + q];
            }
            float mx = l[0];
#pragma unroll
            for (int q = 1; q < 5; q++) mx = fmaxf(mx, l[q]);
            float s = 0.0f, ex[5];
#pragma unroll
            for (int q = 0; q < 5; q++) { ex[q] = expf(l[q] - mx); s += ex[q]; }
            float inv = 1.0f / s;
#pragma unroll
            for (int q = 0; q < 5; q++) out[e * 5 + q] = ex[q] * inv;
        }
    }
}

extern "C" void kernel_launch(void* const* d_in, const int* in_sizes, int n_in,
                              void* d_out, int out_size) {
    const float* x      = (const float*)d_in[0];
    const int*   tei    = (const int*)d_in[1];
    const int*   dei    = (const int*)d_in[2];
    const float* eattr  = (const float*)d_in[3];
    const float* Wroot1 = (const float*)d_in[4];
    const float* Wrel1  = (const float*)d_in[5];
    const float* b1     = (const float*)d_in[6];
    const float* Wroot2 = (const float*)d_in[7];
    const float* Wrel2  = (const float*)d_in[8];
    const float* b2     = (const float*)d_in[9];
    const float* W1     = (const float*)d_in[10];
    const float* bl1    = (const float*)d_in[11];
    const float* W2     = (const float*)d_in[12];
    const float* bl2    = (const float*)d_in[13];
    float* out = (float*)d_out;

    int Etr = in_sizes[1] / 2;
    int Ed  = in_sizes[2] / 2;

    static int smem_set = 0;
    if (!smem_set) {
        cudaFuncSetAttribute(decode_mma_k, cudaFuncAttributeMaxDynamicSharedMemorySize,
                             SMEM_DEC);
        cudaFuncSetAttribute(node1_mma_k, cudaFuncAttributeMaxDynamicSharedMemorySize,
                             N1_SMEM);
        smem_set = 1;
    }

    zero_k<<<(N_NODES * ZDIM + 255) / 256, 256>>>();
    prepB_k<<<(128 * 832 + 255) / 256, 256>>>(W1);
    prepW2_k<<<(128 * 128 + 255) / 256, 256>>>(Wrel2, Wroot2);
    edge1_k<<<(Etr + 255) / 256, 256>>>(tei, tei + Etr, x, Etr);
    node1_mma_k<<<(N_NODES + 63) / 64, 256, N1_SMEM>>>(x, Wroot1, Wrel1, b1);
    {
        long threads = (long)Etr * 16;
        edge2_k<<<(int)((threads + 255) / 256), 256>>>(tei, tei + Etr, Etr);
    }
    node2_k<<<(N_NODES * ZDIM + 255) / 256, 256>>>(b2);
    {
        long threads = (long)Ed * 16;
        pair_k<<<(int)((threads + 255) / 256), 256>>>(dei, dei + Ed, Ed);
    }
    decode_mma_k<<<(Ed + 127) / 128, 256, SMEM_DEC>>>(eattr, bl1, W2, bl2, out, Ed);
}

// round 6
// speedup vs baseline: 2.3929x; 1.0411x over previous
#include <cuda_runtime.h>
#include <cuda_fp16.h>
#include <math.h>
#include <stdint.h>

#define N_NODES 100000
#define ZDIM 64
#define H1 128
#define E_DEC_MAX 200000
#define NB_K 26            // 832 / 32 K-steps for decode GEMM

// ---------------- scratch ----------------
__device__ float g_s1cnt[2 * N_NODES];
__device__ float g_y[N_NODES * ZDIM];
__device__ float g_r[N_NODES * ZDIM];
__device__ float g_z2[N_NODES * ZDIM];
__device__ __half g_Bf[128 * 832];      // W1^T fp16, n-major
__device__ __half g_W2f[128 * 128];     // [Wrel2|Wroot2]^T fp16, n-major

// ---------------- PTX helpers ----------------
static __device__ __forceinline__ void red_add_v2(float* addr, float a, float b) {
    asm volatile("red.global.add.v2.f32 [%0], {%1, %2};"
                 :: "l"(addr), "f"(a), "f"(b) : "memory");
}
static __device__ __forceinline__ void red_add_v4(float* addr, float4 v) {
    asm volatile("red.global.add.v4.f32 [%0], {%1, %2, %3, %4};"
                 :: "l"(addr), "f"(v.x), "f"(v.y), "f"(v.z), "f"(v.w) : "memory");
}
static __device__ __forceinline__ uint32_t smem_u32(const void* p) {
    uint32_t a;
    asm("{ .reg .u64 t; cvta.to.shared.u64 t, %1; cvt.u32.u64 %0, t; }" : "=r"(a) : "l"(p));
    return a;
}
static __device__ __forceinline__ void ldm_x4(uint32_t* r, uint32_t addr) {
    asm volatile("ldmatrix.sync.aligned.m8n8.x4.shared.b16 {%0,%1,%2,%3}, [%4];"
                 : "=r"(r[0]), "=r"(r[1]), "=r"(r[2]), "=r"(r[3]) : "r"(addr));
}
static __device__ __forceinline__ void mma_f16(float* c, const uint32_t* a,
                                               uint32_t b0, uint32_t b1) {
    asm volatile("mma.sync.aligned.m16n8k16.row.col.f32.f16.f16.f32 "
                 "{%0,%1,%2,%3}, {%4,%5,%6,%7}, {%8,%9}, {%0,%1,%2,%3};"
                 : "+f"(c[0]), "+f"(c[1]), "+f"(c[2]), "+f"(c[3])
                 : "r"(a[0]), "r"(a[1]), "r"(a[2]), "r"(a[3]), "r"(b0), "r"(b1));
}
static __device__ __forceinline__ void cp_async16(uint32_t dst, const void* src) {
    asm volatile("cp.async.cg.shared.global [%0], [%1], 16;" :: "r"(dst), "l"(src));
}
static __device__ __forceinline__ void cp_commit() {
    asm volatile("cp.async.commit_group;");
}
static __device__ __forceinline__ void cp_wait0() {
    asm volatile("cp.async.wait_group 0;" ::: "memory");
}

// 8 fp32 -> 8 fp16 (one uint4)
static __device__ __forceinline__ uint4 cvt8h(float4 v0, float4 v1) {
    uint4 o;
    __half2 h0 = __floats2half2_rn(v0.x, v0.y);
    __half2 h1 = __floats2half2_rn(v0.z, v0.w);
    __half2 h2 = __floats2half2_rn(v1.x, v1.y);
    __half2 h3 = __floats2half2_rn(v1.z, v1.w);
    o.x = *(uint32_t*)&h0; o.y = *(uint32_t*)&h1;
    o.z = *(uint32_t*)&h2; o.w = *(uint32_t*)&h3;
    return o;
}

// ---------------- zero scratch ----------------
__global__ void zero_k() {
    int i = blockIdx.x * blockDim.x + threadIdx.x;
    if (i < 2 * N_NODES) g_s1cnt[i] = 0.0f;
    if (i < N_NODES * ZDIM) g_z2[i] = 0.0f;
}

// ---------------- layer-1 edge pass ----------------
__global__ void edge1_k(const int* __restrict__ src, const int* __restrict__ dst,
                        const float* __restrict__ x, int E) {
    int e = blockIdx.x * blockDim.x + threadIdx.x;
    if (e >= E) return;
    int s = src[e], d = dst[e];
    red_add_v2(&g_s1cnt[2 * d], x[s], 1.0f);
}

// ---------------- layer-2 edge scatter ----------------
__global__ void edge2_k(const int* __restrict__ src, const int* __restrict__ dst, int E) {
    int idx = blockIdx.x * blockDim.x + threadIdx.x;
    int e = idx >> 4;
    if (e >= E) return;
    int g = idx & 15;
    int s = src[e], d = dst[e];
    float4 v = ((const float4*)g_y)[s * 16 + g];
    red_add_v4(&g_z2[d * ZDIM + g * 4], v);
}

// ---------------- z2 = relu(r + agg2/cnt + b2) ----------------
__global__ void node2_k(const float* __restrict__ b2) {
    int i = blockIdx.x * blockDim.x + threadIdx.x;
    if (i >= N_NODES * ZDIM) return;
    int n = i >> 6, c = i & 63;
    float cnt = g_s1cnt[2 * n + 1];
    float v = g_r[i] + g_z2[i] / fmaxf(cnt, 1.0f) + b2[c];
    g_z2[i] = fmaxf(v, 0.0f);
}

// ---------------- W1^T fp16 (n-major [128][832]) ----------------
__global__ void prepB_k(const float* __restrict__ W1) {
    int i = blockIdx.x * blockDim.x + threadIdx.x;
    if (i >= 128 * 832) return;
    int n = i / 832, k = i % 832;
    g_Bf[i] = __float2half_rn(W1[k * 128 + n]);
}

// ---------------- [Wrel2|Wroot2]^T fp16 (n-major [128][128]) ----------------
__global__ void prepW2_k(const float* __restrict__ Wrel2, const float* __restrict__ Wroot2) {
    int i = blockIdx.x * blockDim.x + threadIdx.x;
    if (i >= 128 * 128) return;
    int n = i >> 7, k = i & 127;
    float w = (n < 64) ? Wrel2[k * 64 + n] : Wroot2[k * 64 + (n - 64)];
    g_W2f[i] = __float2half_rn(w);
}

// ======== node1 via fp16 mma ========
// z1 = relu(x*Wroot1 + m*Wrel1 + b1); [y|r] = z1 @ [Wrel2|Wroot2]
// CTA 64 nodes x 128 outs, K=128 in 4 chunks of 32.
// smem: A [64][80] fp16 @0 (5120) | B [128][80] fp16 @5120 (10240) | z1 fp32 @15360 (32768)
#define N1_SMEM (15360 + 32768)
__global__ __launch_bounds__(256)
void node1_mma_k(const float* __restrict__ x,
                 const float* __restrict__ Wroot1, const float* __restrict__ Wrel1,
                 const float* __restrict__ b1) {
    extern __shared__ __align__(128) char smem[];
    uint32_t sb = smem_u32(smem);
    float* z1s = (float*)(smem + 15360);
    int tid = threadIdx.x, lane = tid & 31, wid = tid >> 5;
    int wm = wid >> 2, wn = wid & 3;
    int n0 = blockIdx.x * 64;

    {
        int nl = tid >> 2;
        int q  = tid & 3;
        int node = n0 + nl; if (node >= N_NODES) node = N_NODES - 1;
        float xi = x[node];
        float2 sc = ((const float2*)g_s1cnt)[node];
        float m = sc.x / fmaxf(sc.y, 1.0f);
#pragma unroll
        for (int j = 0; j < 32; j++) {
            int c = q * 32 + j;
            z1s[nl * 128 + c] =
                fmaxf(xi * __ldg(Wroot1 + c) + m * __ldg(Wrel1 + c) + __ldg(b1 + c), 0.0f);
        }
    }
    __syncthreads();

    float acc[2][4][4];
#pragma unroll
    for (int a = 0; a < 2; a++)
#pragma unroll
        for (int b = 0; b < 4; b++)
#pragma unroll
            for (int c = 0; c < 4; c++) acc[a][b][c] = 0.0f;

    int arow = tid >> 2;
    int a4 = (tid & 3);

    for (int kb = 0; kb < 4; kb++) {
        // A: convert z1 chunk (each thread 8 k = 16B)
        {
            float4 a0 = *(float4*)&z1s[arow * 128 + kb * 32 + a4 * 8];
            float4 a1 = *(float4*)&z1s[arow * 128 + kb * 32 + a4 * 8 + 4];
            *(uint4*)(smem + arow * 80 + a4 * 16) = cvt8h(a0, a1);
        }
        // B: copy fp16 chunk (8KB)
#pragma unroll
        for (int j = 0; j < 2; j++) {
            int idx = tid * 2 + j;
            int n = idx >> 2, ch = idx & 3;
            *(uint4*)(smem + 5120 + n * 80 + ch * 16) =
                *(const uint4*)((const char*)g_W2f + (size_t)n * 256 + (size_t)kb * 64 + ch * 16);
        }
        __syncthreads();
#pragma unroll
        for (int kh = 0; kh < 2; kh++) {
            uint32_t ah[2][4], bh[2][4];
#pragma unroll
            for (int mt = 0; mt < 2; mt++) {
                int row = wm * 32 + mt * 16 + (lane & 15);
                ldm_x4(ah[mt], sb + row * 80 + kh * 32 + (lane >> 4) * 16);
            }
#pragma unroll
            for (int g = 0; g < 2; g++) {
                int n = wn * 32 + g * 16 + (lane & 15);
                ldm_x4(bh[g], sb + 5120 + n * 80 + kh * 32 + (lane >> 4) * 16);
            }
#pragma unroll
            for (int mt = 0; mt < 2; mt++)
#pragma unroll
                for (int g = 0; g < 2; g++)
#pragma unroll
                    for (int p = 0; p < 2; p++)
                        mma_f16(acc[mt][g * 2 + p], ah[mt], bh[g][p], bh[g][p + 2]);
        }
        __syncthreads();
    }

#pragma unroll
    for (int mt = 0; mt < 2; mt++)
#pragma unroll
        for (int t8 = 0; t8 < 4; t8++) {
            int r0 = wm * 32 + mt * 16 + (lane >> 2);
            int cb = wn * 32 + t8 * 8 + (lane & 3) * 2;
            float* dst = (cb < 64) ? g_y : g_r;
            int c = cb & 63;
#pragma unroll
            for (int half = 0; half < 2; half++) {
                int node = n0 + r0 + half * 8;
                if (node < N_NODES) {
                    dst[node * 64 + c]     = acc[mt][t8][half * 2];
                    dst[node * 64 + c + 1] = acc[mt][t8][half * 2 + 1];
                }
            }
        }
}

// ======== decode GEMM: CTA 128x128, fp16 single-pass, pair gather fused ========
// stage (20480B): A[128][80] fp16 @0, B[128][80] fp16 @10240
// double buffered: 40960B. epilogue: H[128][132] f32 @0 (67584), W2s @67584 (2580).
#define STAGE2_SZ 20480
#define SMEM_DEC 70272

__global__ __launch_bounds__(256)
void decode_mma_k(const int* __restrict__ src, const int* __restrict__ dst,
                  const float* __restrict__ eattr,
                  const float* __restrict__ bl1, const float* __restrict__ W2,
                  const float* __restrict__ bl2,
                  float* __restrict__ out, int E) {
    extern __shared__ __align__(128) char smem[];
    uint32_t sb = smem_u32(smem);
    int tid = threadIdx.x, lane = tid & 31, wid = tid >> 5;
    int wm = wid >> 1, wn = wid & 1;           // warps 4(M) x 2(N), warp tile 32x64
    int e0 = blockIdx.x * 128;

    float acc[2][8][4];
#pragma unroll
    for (int a = 0; a < 2; a++)
#pragma unroll
        for (int b = 0; b < 8; b++)
#pragma unroll
            for (int c = 0; c < 4; c++) acc[a][b][c] = 0.0f;

    int arow = tid >> 1;
    int ahalf = tid & 1;
    int ae = e0 + arow; if (ae >= E) ae = E - 1;
    int esrc = src[ae], edst = dst[ae];

    int bn = tid >> 1;
    int bhalf = tid & 1;

    float4 aR[4];

#define LOAD_A2(kb) do {                                                          \
    int kc = (kb) * 32 + ahalf * 16;                                              \
    if (kc < 64) {                                                                \
        const float4* ps = (const float4*)(g_z2 + (size_t)esrc * 64 + kc);        \
        const float4* pd = (const float4*)(g_z2 + (size_t)edst * 64 + kc);        \
        _Pragma("unroll")                                                         \
        for (int j = 0; j < 4; j++) {                                             \
            float4 a = ps[j], b = pd[j];                                          \
            aR[j] = make_float4(a.x * b.x, a.y * b.y, a.z * b.z, a.w * b.w);      \
        }                                                                         \
    } else {                                                                      \
        const float4* p = (const float4*)(eattr + (size_t)ae * 768 + (kc - 64));  \
        aR[0] = p[0]; aR[1] = p[1]; aR[2] = p[2]; aR[3] = p[3];                   \
    }                                                                             \
} while (0)

#define ISSUE_B2(kb, stagebase) do {                                              \
    const char* s = (const char*)g_Bf + (size_t)bn * 1664 + (size_t)(kb) * 64 + bhalf * 32; \
    uint32_t dh = sb + (stagebase) + 10240 + bn * 80 + bhalf * 32;                \
    cp_async16(dh, s); cp_async16(dh + 16, s + 16);                               \
    cp_commit();                                                                  \
} while (0)

    ISSUE_B2(0, 0);
    LOAD_A2(0);

    for (int kb = 0; kb < NB_K; kb++) {
        int base = (kb & 1) * STAGE2_SZ;
        // STS A (convert 16 fp32 -> 16 fp16 = 32B)
        {
            uint32_t offA = base + arow * 80 + ahalf * 32;
            *(uint4*)(smem + offA)      = cvt8h(aR[0], aR[1]);
            *(uint4*)(smem + offA + 16) = cvt8h(aR[2], aR[3]);
        }
        cp_wait0();
        __syncthreads();
        if (kb + 1 < NB_K) {
            ISSUE_B2(kb + 1, (kb & 1) ? 0 : STAGE2_SZ);
            LOAD_A2(kb + 1);
        }
#pragma unroll
        for (int kh = 0; kh < 2; kh++) {
            uint32_t ah[2][4], bh[4][4];
#pragma unroll
            for (int mt = 0; mt < 2; mt++) {
                int row = wm * 32 + mt * 16 + (lane & 15);
                ldm_x4(ah[mt], sb + base + row * 80 + kh * 32 + (lane >> 4) * 16);
            }
#pragma unroll
            for (int g = 0; g < 4; g++) {
                int n = wn * 64 + g * 16 + (lane & 15);
                ldm_x4(bh[g], sb + base + 10240 + n * 80 + kh * 32 + (lane >> 4) * 16);
            }
#pragma unroll
            for (int mt = 0; mt < 2; mt++)
#pragma unroll
                for (int g = 0; g < 4; g++)
#pragma unroll
                    for (int p = 0; p < 2; p++)
                        mma_f16(acc[mt][g * 2 + p], ah[mt], bh[g][p], bh[g][p + 2]);
        }
        __syncthreads();
    }

    // epilogue
    float* Hs = (float*)smem;
    float* W2s = (float*)(smem + 67584);       // 645 floats
#pragma unroll
    for (int mt = 0; mt < 2; mt++)
#pragma unroll
        for (int g = 0; g < 4; g++)
#pragma unroll
            for (int p = 0; p < 2; p++) {
                int r0 = wm * 32 + mt * 16 + (lane >> 2);
                int cb = wn * 64 + g * 16 + p * 8 + (lane & 3) * 2;
                float b0 = __ldg(bl1 + cb), b1 = __ldg(bl1 + cb + 1);
                float* c = acc[mt][g * 2 + p];
                Hs[r0 * 132 + cb]           = fmaxf(c[0] + b0, 0.0f);
                Hs[r0 * 132 + cb + 1]       = fmaxf(c[1] + b1, 0.0f);
                Hs[(r0 + 8) * 132 + cb]     = fmaxf(c[2] + b0, 0.0f);
                Hs[(r0 + 8) * 132 + cb + 1] = fmaxf(c[3] + b1, 0.0f);
            }
    for (int i = tid; i < 645; i += 256) W2s[i] = (i < 640) ? __ldg(W2 + i) : __ldg(bl2 + i - 640);
    __syncthreads();

    if (tid < 128) {
        int e = e0 + tid;
        if (e < E) {
            float l[5];
#pragma unroll
            for (int q = 0; q < 5; q++) l[q] = W2s[640 + q];
#pragma unroll 4
            for (int k = 0; k < 128; k++) {
                float h = Hs[tid * 132 + k];
#pragma unroll
                for (int q = 0; q < 5; q++) l[q] += h * W2s[k * 5 + q];
            }
            float mx = l[0];
#pragma unroll
            for (int q = 1; q < 5; q++) mx = fmaxf(mx, l[q]);
            float s = 0.0f, ex[5];
#pragma unroll
            for (int q = 0; q < 5; q++) { ex[q] = expf(l[q] - mx); s += ex[q]; }
            float inv = 1.0f / s;
#pragma unroll
            for (int q = 0; q < 5; q++) out[e * 5 + q] = ex[q] * inv;
        }
    }
}

extern "C" void kernel_launch(void* const* d_in, const int* in_sizes, int n_in,
                              void* d_out, int out_size) {
    const float* x      = (const float*)d_in[0];
    const int*   tei    = (const int*)d_in[1];
    const int*   dei    = (const int*)d_in[2];
    const float* eattr  = (const float*)d_in[3];
    const float* Wroot1 = (const float*)d_in[4];
    const float* Wrel1  = (const float*)d_in[5];
    const float* b1     = (const float*)d_in[6];
    const float* Wroot2 = (const float*)d_in[7];
    const float* Wrel2  = (const float*)d_in[8];
    const float* b2     = (const float*)d_in[9];
    const float* W1     = (const float*)d_in[10];
    const float* bl1    = (const float*)d_in[11];
    const float* W2     = (const float*)d_in[12];
    const float* bl2    = (const float*)d_in[13];
    float* out = (float*)d_out;

    int Etr = in_sizes[1] / 2;
    int Ed  = in_sizes[2] / 2;

    static int smem_set = 0;
    if (!smem_set) {
        cudaFuncSetAttribute(decode_mma_k, cudaFuncAttributeMaxDynamicSharedMemorySize,
                             SMEM_DEC);
        cudaFuncSetAttribute(node1_mma_k, cudaFuncAttributeMaxDynamicSharedMemorySize,
                             N1_SMEM);
        smem_set = 1;
    }

    zero_k<<<(N_NODES * ZDIM + 255) / 256, 256>>>();
    prepB_k<<<(128 * 832 + 255) / 256, 256>>>(W1);
    prepW2_k<<<(128 * 128 + 255) / 256, 256>>>(Wrel2, Wroot2);
    edge1_k<<<(Etr + 255) / 256, 256>>>(tei, tei + Etr, x, Etr);
    node1_mma_k<<<(N_NODES + 63) / 64, 256, N1_SMEM>>>(x, Wroot1, Wrel1, b1);
    {
        long threads = (long)Etr * 16;
        edge2_k<<<(int)((threads + 255) / 256), 256>>>(tei, tei + Etr, Etr);
    }
    node2_k<<<(N_NODES * ZDIM + 255) / 256, 256>>>(b2);
    decode_mma_k<<<(Ed + 127) / 128, 256, SMEM_DEC>>>(dei, dei + Ed, eattr,
                                                      bl1, W2, bl2, out, Ed);
}

// round 7
// speedup vs baseline: 3.2037x; 1.3388x over previous
#include <cuda_runtime.h>
#include <cuda_fp16.h>
#include <math.h>
#include <stdint.h>

#define N_NODES 100000
#define ZDIM 64
#define H1 128
#define E_DEC_MAX 200000
#define NB_K 26            // 832 / 32 K-steps for decode GEMM

// ---------------- scratch ----------------
__device__ float g_s1cnt[2 * N_NODES];
__device__ float g_y[N_NODES * ZDIM];
__device__ float g_r[N_NODES * ZDIM];
__device__ float g_z2[N_NODES * ZDIM];
__device__ float g_nrep[E_DEC_MAX * ZDIM];
__device__ __half g_Bf[128 * 832];      // W1^T fp16, n-major
__device__ __half g_W2f[128 * 128];     // [Wrel2|Wroot2]^T fp16, n-major

// ---------------- PTX helpers ----------------
static __device__ __forceinline__ void red_add_v2(float* addr, float a, float b) {
    asm volatile("red.global.add.v2.f32 [%0], {%1, %2};"
                 :: "l"(addr), "f"(a), "f"(b) : "memory");
}
static __device__ __forceinline__ void red_add_v4(float* addr, float4 v) {
    asm volatile("red.global.add.v4.f32 [%0], {%1, %2, %3, %4};"
                 :: "l"(addr), "f"(v.x), "f"(v.y), "f"(v.z), "f"(v.w) : "memory");
}
static __device__ __forceinline__ uint32_t smem_u32(const void* p) {
    uint32_t a;
    asm("{ .reg .u64 t; cvta.to.shared.u64 t, %1; cvt.u32.u64 %0, t; }" : "=r"(a) : "l"(p));
    return a;
}
static __device__ __forceinline__ void ldm_x4(uint32_t* r, uint32_t addr) {
    asm volatile("ldmatrix.sync.aligned.m8n8.x4.shared.b16 {%0,%1,%2,%3}, [%4];"
                 : "=r"(r[0]), "=r"(r[1]), "=r"(r[2]), "=r"(r[3]) : "r"(addr));
}
static __device__ __forceinline__ void mma_f16(float* c, const uint32_t* a,
                                               uint32_t b0, uint32_t b1) {
    asm volatile("mma.sync.aligned.m16n8k16.row.col.f32.f16.f16.f32 "
                 "{%0,%1,%2,%3}, {%4,%5,%6,%7}, {%8,%9}, {%0,%1,%2,%3};"
                 : "+f"(c[0]), "+f"(c[1]), "+f"(c[2]), "+f"(c[3])
                 : "r"(a[0]), "r"(a[1]), "r"(a[2]), "r"(a[3]), "r"(b0), "r"(b1));
}
static __device__ __forceinline__ void cp_async16(uint32_t dst, const void* src) {
    asm volatile("cp.async.cg.shared.global [%0], [%1], 16;" :: "r"(dst), "l"(src));
}
static __device__ __forceinline__ void cp_commit() {
    asm volatile("cp.async.commit_group;");
}
static __device__ __forceinline__ void cp_wait0() {
    asm volatile("cp.async.wait_group 0;" ::: "memory");
}
static __device__ __forceinline__ void cp_wait1() {
    asm volatile("cp.async.wait_group 1;" ::: "memory");
}

// 8 fp32 -> 8 fp16 (one uint4)
static __device__ __forceinline__ uint4 cvt8h(float4 v0, float4 v1) {
    uint4 o;
    __half2 h0 = __floats2half2_rn(v0.x, v0.y);
    __half2 h1 = __floats2half2_rn(v0.z, v0.w);
    __half2 h2 = __floats2half2_rn(v1.x, v1.y);
    __half2 h3 = __floats2half2_rn(v1.z, v1.w);
    o.x = *(uint32_t*)&h0; o.y = *(uint32_t*)&h1;
    o.z = *(uint32_t*)&h2; o.w = *(uint32_t*)&h3;
    return o;
}

// ---------------- zero scratch ----------------
__global__ void zero_k() {
    int i = blockIdx.x * blockDim.x + threadIdx.x;
    if (i < 2 * N_NODES) g_s1cnt[i] = 0.0f;
    if (i < N_NODES * ZDIM) g_z2[i] = 0.0f;
}

// ---------------- layer-1 edge pass ----------------
__global__ void edge1_k(const int* __restrict__ src, const int* __restrict__ dst,
                        const float* __restrict__ x, int E) {
    int e = blockIdx.x * blockDim.x + threadIdx.x;
    if (e >= E) return;
    int s = src[e], d = dst[e];
    red_add_v2(&g_s1cnt[2 * d], x[s], 1.0f);
}

// ---------------- layer-2 edge scatter ----------------
__global__ void edge2_k(const int* __restrict__ src, const int* __restrict__ dst, int E) {
    int idx = blockIdx.x * blockDim.x + threadIdx.x;
    int e = idx >> 4;
    if (e >= E) return;
    int g = idx & 15;
    int s = src[e], d = dst[e];
    float4 v = ((const float4*)g_y)[s * 16 + g];
    red_add_v4(&g_z2[d * ZDIM + g * 4], v);
}

// ---------------- z2 = relu(r + agg2/cnt + b2) ----------------
__global__ void node2_k(const float* __restrict__ b2) {
    int i = blockIdx.x * blockDim.x + threadIdx.x;
    if (i >= N_NODES * ZDIM) return;
    int n = i >> 6, c = i & 63;
    float cnt = g_s1cnt[2 * n + 1];
    float v = g_r[i] + g_z2[i] / fmaxf(cnt, 1.0f) + b2[c];
    g_z2[i] = fmaxf(v, 0.0f);
}

// ---------------- decode pair gather: nrep = z2[src]*z2[dst] (fp32) ----------------
__global__ void pair_k(const int* __restrict__ src, const int* __restrict__ dst, int E) {
    int idx = blockIdx.x * blockDim.x + threadIdx.x;
    int e = idx >> 4;
    if (e >= E) return;
    int g = idx & 15;
    int s = src[e], d = dst[e];
    float4 a = ((const float4*)g_z2)[s * 16 + g];
    float4 b = ((const float4*)g_z2)[d * 16 + g];
    float4 o;
    o.x = a.x * b.x; o.y = a.y * b.y; o.z = a.z * b.z; o.w = a.w * b.w;
    ((float4*)g_nrep)[e * 16 + g] = o;
}

// ---------------- W1^T fp16 (n-major [128][832]) ----------------
__global__ void prepB_k(const float* __restrict__ W1) {
    int i = blockIdx.x * blockDim.x + threadIdx.x;
    if (i >= 128 * 832) return;
    int n = i / 832, k = i % 832;
    g_Bf[i] = __float2half_rn(W1[k * 128 + n]);
}

// ---------------- [Wrel2|Wroot2]^T fp16 (n-major [128][128]) ----------------
__global__ void prepW2_k(const float* __restrict__ Wrel2, const float* __restrict__ Wroot2) {
    int i = blockIdx.x * blockDim.x + threadIdx.x;
    if (i >= 128 * 128) return;
    int n = i >> 7, k = i & 127;
    float w = (n < 64) ? Wrel2[k * 64 + n] : Wroot2[k * 64 + (n - 64)];
    g_W2f[i] = __float2half_rn(w);
}

// ======== node1 via fp16 mma (unchanged from R6) ========
#define N1_SMEM (15360 + 32768)
__global__ __launch_bounds__(256)
void node1_mma_k(const float* __restrict__ x,
                 const float* __restrict__ Wroot1, const float* __restrict__ Wrel1,
                 const float* __restrict__ b1) {
    extern __shared__ __align__(128) char smem[];
    uint32_t sb = smem_u32(smem);
    float* z1s = (float*)(smem + 15360);
    int tid = threadIdx.x, lane = tid & 31, wid = tid >> 5;
    int wm = wid >> 2, wn = wid & 3;
    int n0 = blockIdx.x * 64;

    {
        int nl = tid >> 2;
        int q  = tid & 3;
        int node = n0 + nl; if (node >= N_NODES) node = N_NODES - 1;
        float xi = x[node];
        float2 sc = ((const float2*)g_s1cnt)[node];
        float m = sc.x / fmaxf(sc.y, 1.0f);
#pragma unroll
        for (int j = 0; j < 32; j++) {
            int c = q * 32 + j;
            z1s[nl * 128 + c] =
                fmaxf(xi * __ldg(Wroot1 + c) + m * __ldg(Wrel1 + c) + __ldg(b1 + c), 0.0f);
        }
    }
    __syncthreads();

    float acc[2][4][4];
#pragma unroll
    for (int a = 0; a < 2; a++)
#pragma unroll
        for (int b = 0; b < 4; b++)
#pragma unroll
            for (int c = 0; c < 4; c++) acc[a][b][c] = 0.0f;

    int arow = tid >> 2;
    int a4 = (tid & 3);

    for (int kb = 0; kb < 4; kb++) {
        {
            float4 a0 = *(float4*)&z1s[arow * 128 + kb * 32 + a4 * 8];
            float4 a1 = *(float4*)&z1s[arow * 128 + kb * 32 + a4 * 8 + 4];
            *(uint4*)(smem + arow * 80 + a4 * 16) = cvt8h(a0, a1);
        }
#pragma unroll
        for (int j = 0; j < 2; j++) {
            int idx = tid * 2 + j;
            int n = idx >> 2, ch = idx & 3;
            *(uint4*)(smem + 5120 + n * 80 + ch * 16) =
                *(const uint4*)((const char*)g_W2f + (size_t)n * 256 + (size_t)kb * 64 + ch * 16);
        }
        __syncthreads();
#pragma unroll
        for (int kh = 0; kh < 2; kh++) {
            uint32_t ah[2][4], bh[2][4];
#pragma unroll
            for (int mt = 0; mt < 2; mt++) {
                int row = wm * 32 + mt * 16 + (lane & 15);
                ldm_x4(ah[mt], sb + row * 80 + kh * 32 + (lane >> 4) * 16);
            }
#pragma unroll
            for (int g = 0; g < 2; g++) {
                int n = wn * 32 + g * 16 + (lane & 15);
                ldm_x4(bh[g], sb + 5120 + n * 80 + kh * 32 + (lane >> 4) * 16);
            }
#pragma unroll
            for (int mt = 0; mt < 2; mt++)
#pragma unroll
                for (int g = 0; g < 2; g++)
#pragma unroll
                    for (int p = 0; p < 2; p++)
                        mma_f16(acc[mt][g * 2 + p], ah[mt], bh[g][p], bh[g][p + 2]);
        }
        __syncthreads();
    }

#pragma unroll
    for (int mt = 0; mt < 2; mt++)
#pragma unroll
        for (int t8 = 0; t8 < 4; t8++) {
            int r0 = wm * 32 + mt * 16 + (lane >> 2);
            int cb = wn * 32 + t8 * 8 + (lane & 3) * 2;
            float* dst = (cb < 64) ? g_y : g_r;
            int c = cb & 63;
#pragma unroll
            for (int half = 0; half < 2; half++) {
                int node = n0 + r0 + half * 8;
                if (node < N_NODES) {
                    dst[node * 64 + c]     = acc[mt][t8][half * 2];
                    dst[node * 64 + c + 1] = acc[mt][t8][half * 2 + 1];
                }
            }
        }
}

// ======== decode GEMM v3: 3-stage cp.async multistage, fp16 mma ========
// smem:
//   A32 ring:  3 x 16384 @ 0       (fp32 A staging, cp.async)
//   B ring:    3 x 10240 @ 49152   (fp16 B, cp.async)
//   A16 ring:  2 x 10240 @ 79872   (fp16 A, converted)
//   W2s:       2580      @ 100352
// epilogue reuses [0, 67584) for H[128][132] fp32.
#define A32_OFF 0
#define B_OFF   49152
#define A16_OFF 79872
#define W2S_OFF 100352
#define SMEM_DEC 102944

__global__ __launch_bounds__(256, 2)
void decode_mma_k(const float* __restrict__ eattr,
                  const float* __restrict__ bl1, const float* __restrict__ W2,
                  const float* __restrict__ bl2,
                  float* __restrict__ out, int E) {
    extern __shared__ __align__(128) char smem[];
    uint32_t sb = smem_u32(smem);
    int tid = threadIdx.x, lane = tid & 31, wid = tid >> 5;
    int wm = wid >> 1, wn = wid & 1;           // warps 4(M) x 2(N), warp tile 32x64
    int e0 = blockIdx.x * 128;

    float acc[2][8][4];
#pragma unroll
    for (int a = 0; a < 2; a++)
#pragma unroll
        for (int b = 0; b < 8; b++)
#pragma unroll
            for (int c = 0; c < 4; c++) acc[a][b][c] = 0.0f;

    int arow = tid >> 1;         // 0..127
    int ahalf = tid & 1;         // 16-float half of the 32-float K step
    int ae = e0 + arow; if (ae >= E) ae = E - 1;

#define ISSUE(kb) do {                                                            \
    int _s = (kb) % 3;                                                            \
    /* A: fp32, 64B per thread */                                                 \
    const char* asrc = ((kb) < 2)                                                 \
        ? (const char*)(g_nrep + (size_t)ae * 64 + (kb) * 32 + ahalf * 16)        \
        : (const char*)(eattr + (size_t)ae * 768 + ((kb) - 2) * 32 + ahalf * 16); \
    uint32_t adst = sb + A32_OFF + _s * 16384 + arow * 128 + ahalf * 64;          \
    cp_async16(adst,      asrc);                                                  \
    cp_async16(adst + 16, asrc + 16);                                             \
    cp_async16(adst + 32, asrc + 32);                                             \
    cp_async16(adst + 48, asrc + 48);                                             \
    /* B: fp16, 32B per thread */                                                 \
    const char* bsrc = (const char*)g_Bf + (size_t)arow * 1664 + (size_t)(kb) * 64 + ahalf * 32; \
    uint32_t bdst = sb + B_OFF + _s * 10240 + arow * 80 + ahalf * 32;             \
    cp_async16(bdst, bsrc); cp_async16(bdst + 16, bsrc + 16);                     \
    cp_commit();                                                                  \
} while (0)

    ISSUE(0);
    ISSUE(1);

    int s3 = 0;
    for (int kb = 0; kb < NB_K; kb++) {
        if (kb == NB_K - 1) cp_wait0(); else cp_wait1();
        __syncthreads();                       // stage s3 visible to all
        // convert A fp32 -> fp16 staging (16 floats per thread)
        {
            const char* a32 = smem + A32_OFF + s3 * 16384 + arow * 128 + ahalf * 64;
            float4 v0 = ((const float4*)a32)[0];
            float4 v1 = ((const float4*)a32)[1];
            float4 v2 = ((const float4*)a32)[2];
            float4 v3 = ((const float4*)a32)[3];
            uint32_t a16 = (uint32_t)(A16_OFF + (kb & 1) * 10240 + arow * 80 + ahalf * 32);
            *(uint4*)(smem + a16)      = cvt8h(v0, v1);
            *(uint4*)(smem + a16 + 16) = cvt8h(v2, v3);
        }
        __syncthreads();                       // A16 ready; all reads of stage s3's A32 done
        if (kb + 2 < NB_K) ISSUE(kb + 2);      // safe: stage (kb+2)%3 last read at iter kb-1
        uint32_t a16b = sb + A16_OFF + (kb & 1) * 10240;
        uint32_t bbase = sb + B_OFF + s3 * 10240;
#pragma unroll
        for (int kh = 0; kh < 2; kh++) {
            uint32_t ah[2][4], bh[4][4];
#pragma unroll
            for (int mt = 0; mt < 2; mt++) {
                int row = wm * 32 + mt * 16 + (lane & 15);
                ldm_x4(ah[mt], a16b + row * 80 + kh * 32 + (lane >> 4) * 16);
            }
#pragma unroll
            for (int g = 0; g < 4; g++) {
                int n = wn * 64 + g * 16 + (lane & 15);
                ldm_x4(bh[g], bbase + n * 80 + kh * 32 + (lane >> 4) * 16);
            }
#pragma unroll
            for (int mt = 0; mt < 2; mt++)
#pragma unroll
                for (int g = 0; g < 4; g++)
#pragma unroll
                    for (int p = 0; p < 2; p++)
                        mma_f16(acc[mt][g * 2 + p], ah[mt], bh[g][p], bh[g][p + 2]);
        }
        s3 = (s3 == 2) ? 0 : s3 + 1;
    }
    __syncthreads();

    // epilogue: H = relu(acc + bl1) -> smem, then 128->5 head + softmax
    float* Hs = (float*)smem;
    float* W2s = (float*)(smem + W2S_OFF);     // 645 floats
#pragma unroll
    for (int mt = 0; mt < 2; mt++)
#pragma unroll
        for (int g = 0; g < 4; g++)
#pragma unroll
            for (int p = 0; p < 2; p++) {
                int r0 = wm * 32 + mt * 16 + (lane >> 2);
                int cb = wn * 64 + g * 16 + p * 8 + (lane & 3) * 2;
                float b0 = __ldg(bl1 + cb), b1 = __ldg(bl1 + cb + 1);
                float* c = acc[mt][g * 2 + p];
                Hs[r0 * 132 + cb]           = fmaxf(c[0] + b0, 0.0f);
                Hs[r0 * 132 + cb + 1]       = fmaxf(c[1] + b1, 0.0f);
                Hs[(r0 + 8) * 132 + cb]     = fmaxf(c[2] + b0, 0.0f);
                Hs[(r0 + 8) * 132 + cb + 1] = fmaxf(c[3] + b1, 0.0f);
            }
    for (int i = tid; i < 645; i += 256) W2s[i] = (i < 640) ? __ldg(W2 + i) : __ldg(bl2 + i - 640);
    __syncthreads();

    if (tid < 128) {
        int e = e0 + tid;
        if (e < E) {
            float l[5];
#pragma unroll
            for (int q = 0; q < 5; q++) l[q] = W2s[640 + q];
#pragma unroll 4
            for (int k = 0; k < 128; k++) {
                float h = Hs[tid * 132 + k];
#pragma unroll
                for (int q = 0; q < 5; q++) l[q] += h * W2s[k * 5 + q];
            }
            float mx = l[0];
#pragma unroll
            for (int q = 1; q < 5; q++) mx = fmaxf(mx, l[q]);
            float s = 0.0f, ex[5];
#pragma unroll
            for (int q = 0; q < 5; q++) { ex[q] = expf(l[q] - mx); s += ex[q]; }
            float inv = 1.0f / s;
#pragma unroll
            for (int q = 0; q < 5; q++) out[e * 5 + q] = ex[q] * inv;
        }
    }
}

extern "C" void kernel_launch(void* const* d_in, const int* in_sizes, int n_in,
                              void* d_out, int out_size) {
    const float* x      = (const float*)d_in[0];
    const int*   tei    = (const int*)d_in[1];
    const int*   dei    = (const int*)d_in[2];
    const float* eattr  = (const float*)d_in[3];
    const float* Wroot1 = (const float*)d_in[4];
    const float* Wrel1  = (const float*)d_in[5];
    const float* b1     = (const float*)d_in[6];
    const float* Wroot2 = (const float*)d_in[7];
    const float* Wrel2  = (const float*)d_in[8];
    const float* b2     = (const float*)d_in[9];
    const float* W1     = (const float*)d_in[10];
    const float* bl1    = (const float*)d_in[11];
    const float* W2     = (const float*)d_in[12];
    const float* bl2    = (const float*)d_in[13];
    float* out = (float*)d_out;

    int Etr = in_sizes[1] / 2;
    int Ed  = in_sizes[2] / 2;

    static int smem_set = 0;
    if (!smem_set) {
        cudaFuncSetAttribute(decode_mma_k, cudaFuncAttributeMaxDynamicSharedMemorySize,
                             SMEM_DEC);
        cudaFuncSetAttribute(node1_mma_k, cudaFuncAttributeMaxDynamicSharedMemorySize,
                             N1_SMEM);
        smem_set = 1;
    }

    zero_k<<<(N_NODES * ZDIM + 255) / 256, 256>>>();
    prepB_k<<<(128 * 832 + 255) / 256, 256>>>(W1);
    prepW2_k<<<(128 * 128 + 255) / 256, 256>>>(Wrel2, Wroot2);
    edge1_k<<<(Etr + 255) / 256, 256>>>(tei, tei + Etr, x, Etr);
    node1_mma_k<<<(N_NODES + 63) / 64, 256, N1_SMEM>>>(x, Wroot1, Wrel1, b1);
    {
        long threads = (long)Etr * 16;
        edge2_k<<<(int)((threads + 255) / 256), 256>>>(tei, tei + Etr, Etr);
    }
    node2_k<<<(N_NODES * ZDIM + 255) / 256, 256>>>(b2);
    {
        long threads = (long)Ed * 16;
        pair_k<<<(int)((threads + 255) / 256), 256>>>(dei, dei + Ed, Ed);
    }
    decode_mma_k<<<(Ed + 127) / 128, 256, SMEM_DEC>>>(eattr, bl1, W2, bl2, out, Ed);
}

// round 9
// speedup vs baseline: 3.4116x; 1.0649x over previous
#include <cuda_runtime.h>
#include <cuda_fp16.h>
#include <math.h>
#include <stdint.h>

#define N_NODES 100000
#define ZDIM 64
#define H1 128
#define E_DEC_MAX 200000
#define NB_K 26            // 832 / 32 K-steps for decode GEMM

// ---------------- scratch ----------------
__device__ float g_s1cnt[2 * N_NODES];
__device__ float g_y[N_NODES * ZDIM];
__device__ float g_r[N_NODES * ZDIM];
__device__ float g_z2[N_NODES * ZDIM];
__device__ float g_nrep[E_DEC_MAX * ZDIM];
__device__ __half g_Bf[128 * 832];      // W1^T fp16, n-major
__device__ __half g_W2f[128 * 128];     // [Wrel2|Wroot2]^T fp16, n-major

// ---------------- PTX helpers ----------------
static __device__ __forceinline__ void red_add_v2(float* addr, float a, float b) {
    asm volatile("red.global.add.v2.f32 [%0], {%1, %2};"
                 :: "l"(addr), "f"(a), "f"(b) : "memory");
}
static __device__ __forceinline__ void red_add_v4(float* addr, float4 v) {
    asm volatile("red.global.add.v4.f32 [%0], {%1, %2, %3, %4};"
                 :: "l"(addr), "f"(v.x), "f"(v.y), "f"(v.z), "f"(v.w) : "memory");
}
static __device__ __forceinline__ uint32_t smem_u32(const void* p) {
    uint32_t a;
    asm("{ .reg .u64 t; cvta.to.shared.u64 t, %1; cvt.u32.u64 %0, t; }" : "=r"(a) : "l"(p));
    return a;
}
static __device__ __forceinline__ void ldm_x4(uint32_t* r, uint32_t addr) {
    asm volatile("ldmatrix.sync.aligned.m8n8.x4.shared.b16 {%0,%1,%2,%3}, [%4];"
                 : "=r"(r[0]), "=r"(r[1]), "=r"(r[2]), "=r"(r[3]) : "r"(addr));
}
static __device__ __forceinline__ void mma_f16(float* c, const uint32_t* a,
                                               uint32_t b0, uint32_t b1) {
    asm volatile("mma.sync.aligned.m16n8k16.row.col.f32.f16.f16.f32 "
                 "{%0,%1,%2,%3}, {%4,%5,%6,%7}, {%8,%9}, {%0,%1,%2,%3};"
                 : "+f"(c[0]), "+f"(c[1]), "+f"(c[2]), "+f"(c[3])
                 : "r"(a[0]), "r"(a[1]), "r"(a[2]), "r"(a[3]), "r"(b0), "r"(b1));
}
static __device__ __forceinline__ void cp_async16(uint32_t dst, const void* src) {
    asm volatile("cp.async.cg.shared.global [%0], [%1], 16;" :: "r"(dst), "l"(src));
}
static __device__ __forceinline__ void cp_commit() {
    asm volatile("cp.async.commit_group;");
}
static __device__ __forceinline__ void cp_wait0() {
    asm volatile("cp.async.wait_group 0;" ::: "memory");
}
static __device__ __forceinline__ void cp_wait1() {
    asm volatile("cp.async.wait_group 1;" ::: "memory");
}

// 8 fp32 -> 8 fp16 (one uint4)
static __device__ __forceinline__ uint4 cvt8h(float4 v0, float4 v1) {
    uint4 o;
    __half2 h0 = __floats2half2_rn(v0.x, v0.y);
    __half2 h1 = __floats2half2_rn(v0.z, v0.w);
    __half2 h2 = __floats2half2_rn(v1.x, v1.y);
    __half2 h3 = __floats2half2_rn(v1.z, v1.w);
    o.x = *(uint32_t*)&h0; o.y = *(uint32_t*)&h1;
    o.z = *(uint32_t*)&h2; o.w = *(uint32_t*)&h3;
    return o;
}

// ---------------- zero scratch ----------------
__global__ void zero_k() {
    int i = blockIdx.x * blockDim.x + threadIdx.x;
    if (i < 2 * N_NODES) g_s1cnt[i] = 0.0f;
    if (i < N_NODES * ZDIM) g_z2[i] = 0.0f;
}

// ---------------- layer-1 edge pass ----------------
__global__ void edge1_k(const int* __restrict__ src, const int* __restrict__ dst,
                        const float* __restrict__ x, int E) {
    int e = blockIdx.x * blockDim.x + threadIdx.x;
    if (e >= E) return;
    int s = src[e], d = dst[e];
    red_add_v2(&g_s1cnt[2 * d], x[s], 1.0f);
}

// ---------------- layer-2 edge scatter ----------------
__global__ void edge2_k(const int* __restrict__ src, const int* __restrict__ dst, int E) {
    int idx = blockIdx.x * blockDim.x + threadIdx.x;
    int e = idx >> 4;
    if (e >= E) return;
    int g = idx & 15;
    int s = src[e], d = dst[e];
    float4 v = ((const float4*)g_y)[s * 16 + g];
    red_add_v4(&g_z2[d * ZDIM + g * 4], v);
}

// ---------------- z2 = relu(r + agg2/cnt + b2) ----------------
__global__ void node2_k(const float* __restrict__ b2) {
    int i = blockIdx.x * blockDim.x + threadIdx.x;
    if (i >= N_NODES * ZDIM) return;
    int n = i >> 6, c = i & 63;
    float cnt = g_s1cnt[2 * n + 1];
    float v = g_r[i] + g_z2[i] / fmaxf(cnt, 1.0f) + b2[c];
    g_z2[i] = fmaxf(v, 0.0f);
}

// ---------------- decode pair gather ----------------
__global__ void pair_k(const int* __restrict__ src, const int* __restrict__ dst, int E) {
    int idx = blockIdx.x * blockDim.x + threadIdx.x;
    int e = idx >> 4;
    if (e >= E) return;
    int g = idx & 15;
    int s = src[e], d = dst[e];
    float4 a = ((const float4*)g_z2)[s * 16 + g];
    float4 b = ((const float4*)g_z2)[d * 16 + g];
    float4 o;
    o.x = a.x * b.x; o.y = a.y * b.y; o.z = a.z * b.z; o.w = a.w * b.w;
    ((float4*)g_nrep)[e * 16 + g] = o;
}

// ---------------- W1^T fp16 (n-major [128][832]) ----------------
__global__ void prepB_k(const float* __restrict__ W1) {
    int i = blockIdx.x * blockDim.x + threadIdx.x;
    if (i >= 128 * 832) return;
    int n = i / 832, k = i % 832;
    g_Bf[i] = __float2half_rn(W1[k * 128 + n]);
}

// ---------------- [Wrel2|Wroot2]^T fp16 (n-major [128][128]) ----------------
__global__ void prepW2_k(const float* __restrict__ Wrel2, const float* __restrict__ Wroot2) {
    int i = blockIdx.x * blockDim.x + threadIdx.x;
    if (i >= 128 * 128) return;
    int n = i >> 7, k = i & 127;
    float w = (n < 64) ? Wrel2[k * 64 + n] : Wroot2[k * 64 + (n - 64)];
    g_W2f[i] = __float2half_rn(w);
}

// ======== node1 v2: single-phase smem, 1 sync ========
// smem: A16 [64 rows][272B] @0 (17408) | B16 [128 rows][272B] @17408 (34816)
#define N1_A_STRIDE 272
#define N1_B_OFF 17408
#define N1_SMEM (17408 + 34816)
__global__ __launch_bounds__(256)
void node1_mma_k(const float* __restrict__ x,
                 const float* __restrict__ Wroot1, const float* __restrict__ Wrel1,
                 const float* __restrict__ b1) {
    extern __shared__ __align__(128) char smem[];
    uint32_t sb = smem_u32(smem);
    int tid = threadIdx.x, lane = tid & 31, wid = tid >> 5;
    int wm = wid >> 2, wn = wid & 3;           // 2(M) x 4(N), warp tile 32x32
    int n0 = blockIdx.x * 64;

    // compute z1 directly to fp16 A tile: thread -> (node nl, 32 channels q*32..)
    {
        int nl = tid >> 2;
        int q  = tid & 3;
        int node = n0 + nl; if (node >= N_NODES) node = N_NODES - 1;
        float xi = x[node];
        float2 sc = ((const float2*)g_s1cnt)[node];
        float m = sc.x / fmaxf(sc.y, 1.0f);
        uint32_t* dst = (uint32_t*)(smem + nl * N1_A_STRIDE + q * 64);
#pragma unroll
        for (int j = 0; j < 16; j++) {
            int c = q * 32 + j * 2;
            float z0  = fmaxf(xi * __ldg(Wroot1 + c)     + m * __ldg(Wrel1 + c)     + __ldg(b1 + c), 0.0f);
            float z1v = fmaxf(xi * __ldg(Wroot1 + c + 1) + m * __ldg(Wrel1 + c + 1) + __ldg(b1 + c + 1), 0.0f);
            __half2 h = __floats2half2_rn(z0, z1v);
            dst[j] = *(uint32_t*)&h;
        }
    }
    // B: copy full 128x128 fp16 (32KB) into 272B-stride rows
#pragma unroll
    for (int i = 0; i < 8; i++) {
        int idx = tid + i * 256;               // 0..2047
        int row = idx >> 4, ch = idx & 15;
        *(uint4*)(smem + N1_B_OFF + row * N1_A_STRIDE + ch * 16) =
            *(const uint4*)((const char*)g_W2f + (size_t)row * 256 + ch * 16);
    }
    __syncthreads();

    float acc[2][4][4];
#pragma unroll
    for (int a = 0; a < 2; a++)
#pragma unroll
        for (int b = 0; b < 4; b++)
#pragma unroll
            for (int c = 0; c < 4; c++) acc[a][b][c] = 0.0f;

#pragma unroll
    for (int kh = 0; kh < 8; kh++) {
        uint32_t ah[2][4], bh[2][4];
#pragma unroll
        for (int mt = 0; mt < 2; mt++) {
            int row = wm * 32 + mt * 16 + (lane & 15);
            ldm_x4(ah[mt], sb + row * N1_A_STRIDE + kh * 32 + (lane >> 4) * 16);
        }
#pragma unroll
        for (int g = 0; g < 2; g++) {
            int n = wn * 32 + g * 16 + (lane & 15);
            ldm_x4(bh[g], sb + N1_B_OFF + n * N1_A_STRIDE + kh * 32 + (lane >> 4) * 16);
        }
#pragma unroll
        for (int mt = 0; mt < 2; mt++)
#pragma unroll
            for (int g = 0; g < 2; g++)
#pragma unroll
                for (int p = 0; p < 2; p++)
                    mma_f16(acc[mt][g * 2 + p], ah[mt], bh[g][p], bh[g][p + 2]);
    }

#pragma unroll
    for (int mt = 0; mt < 2; mt++)
#pragma unroll
        for (int t8 = 0; t8 < 4; t8++) {
            int r0 = wm * 32 + mt * 16 + (lane >> 2);
            int cb = wn * 32 + t8 * 8 + (lane & 3) * 2;
            float* dst = (cb < 64) ? g_y : g_r;
            int c = cb & 63;
#pragma unroll
            for (int half = 0; half < 2; half++) {
                int node = n0 + r0 + half * 8;
                if (node < N_NODES) {
                    dst[node * 64 + c]     = acc[mt][t8][half * 2];
                    dst[node * 64 + c + 1] = acc[mt][t8][half * 2 + 1];
                }
            }
        }
}

// ======== decode GEMM v4: 3-stage cp.async, fp16 mma, 1 sync per K-step ========
#define A32_OFF 0
#define B_OFF   49152
#define A16_OFF 79872
#define W2S_OFF 100352
#define SMEM_DEC 102944

__global__ __launch_bounds__(256, 2)
void decode_mma_k(const float* __restrict__ eattr,
                  const float* __restrict__ bl1, const float* __restrict__ W2,
                  const float* __restrict__ bl2,
                  float* __restrict__ out, int E) {
    extern __shared__ __align__(128) char smem[];
    uint32_t sb = smem_u32(smem);
    int tid = threadIdx.x, lane = tid & 31, wid = tid >> 5;
    int wm = wid >> 1, wn = wid & 1;           // warps 4(M) x 2(N), warp tile 32x64
    int e0 = blockIdx.x * 128;

    float acc[2][8][4];
#pragma unroll
    for (int a = 0; a < 2; a++)
#pragma unroll
        for (int b = 0; b < 8; b++)
#pragma unroll
            for (int c = 0; c < 4; c++) acc[a][b][c] = 0.0f;

    int arow = tid >> 1;         // 0..127
    int ahalf = tid & 1;
    int ae = e0 + arow; if (ae >= E) ae = E - 1;

#define ISSUE(kb) do {                                                            \
    int _s = (kb) % 3;                                                            \
    const char* asrc = ((kb) < 2)                                                 \
        ? (const char*)(g_nrep + (size_t)ae * 64 + (kb) * 32 + ahalf * 16)        \
        : (const char*)(eattr + (size_t)ae * 768 + ((kb) - 2) * 32 + ahalf * 16); \
    uint32_t adst = sb + A32_OFF + _s * 16384 + arow * 128 + ahalf * 64;          \
    cp_async16(adst,      asrc);                                                  \
    cp_async16(adst + 16, asrc + 16);                                             \
    cp_async16(adst + 32, asrc + 32);                                             \
    cp_async16(adst + 48, asrc + 48);                                             \
    const char* bsrc = (const char*)g_Bf + (size_t)arow * 1664 + (size_t)(kb) * 64 + ahalf * 32; \
    uint32_t bdst = sb + B_OFF + _s * 10240 + arow * 80 + ahalf * 32;             \
    cp_async16(bdst, bsrc); cp_async16(bdst + 16, bsrc + 16);                     \
    cp_commit();                                                                  \
} while (0)

    ISSUE(0);
    ISSUE(1);

    int s3 = 0;
    for (int kb = 0; kb < NB_K; kb++) {
        if (kb == NB_K - 1) cp_wait0(); else cp_wait1();
        // convert own A32 bytes (issued by this thread; visible after wait) -> A16
        {
            const char* a32 = smem + A32_OFF + s3 * 16384 + arow * 128 + ahalf * 64;
            float4 v0 = ((const float4*)a32)[0];
            float4 v1 = ((const float4*)a32)[1];
            float4 v2 = ((const float4*)a32)[2];
            float4 v3 = ((const float4*)a32)[3];
            uint32_t a16 = (uint32_t)(A16_OFF + (kb & 1) * 10240 + arow * 80 + ahalf * 32);
            *(uint4*)(smem + a16)      = cvt8h(v0, v1);
            *(uint4*)(smem + a16 + 16) = cvt8h(v2, v3);
        }
        __syncthreads();                       // A16 + B stage visible to all
        if (kb + 2 < NB_K) ISSUE(kb + 2);
        uint32_t a16b = sb + A16_OFF + (kb & 1) * 10240;
        uint32_t bbase = sb + B_OFF + s3 * 10240;
#pragma unroll
        for (int kh = 0; kh < 2; kh++) {
            uint32_t ah[2][4], bh[4][4];
#pragma unroll
            for (int mt = 0; mt < 2; mt++) {
                int row = wm * 32 + mt * 16 + (lane & 15);
                ldm_x4(ah[mt], a16b + row * 80 + kh * 32 + (lane >> 4) * 16);
            }
#pragma unroll
            for (int g = 0; g < 4; g++) {
                int n = wn * 64 + g * 16 + (lane & 15);
                ldm_x4(bh[g], bbase + n * 80 + kh * 32 + (lane >> 4) * 16);
            }
#pragma unroll
            for (int mt = 0; mt < 2; mt++)
#pragma unroll
                for (int g = 0; g < 4; g++)
#pragma unroll
                    for (int p = 0; p < 2; p++)
                        mma_f16(acc[mt][g * 2 + p], ah[mt], bh[g][p], bh[g][p + 2]);
        }
        s3 = (s3 == 2) ? 0 : s3 + 1;
    }
    __syncthreads();

    // epilogue
    float* Hs = (float*)smem;
    float* W2s = (float*)(smem + W2S_OFF);
#pragma unroll
    for (int mt = 0; mt < 2; mt++)
#pragma unroll
        for (int g = 0; g < 4; g++)
#pragma unroll
            for (int p = 0; p < 2; p++) {
                int r0 = wm * 32 + mt * 16 + (lane >> 2);
                int cb = wn * 64 + g * 16 + p * 8 + (lane & 3) * 2;
                float b0 = __ldg(bl1 + cb), b1 = __ldg(bl1 + cb + 1);
                float* c = acc[mt][g * 2 + p];
                Hs[r0 * 132 + cb]           = fmaxf(c[0] + b0, 0.0f);
                Hs[r0 * 132 + cb + 1]       = fmaxf(c[1] + b1, 0.0f);
                Hs[(r0 + 8) * 132 + cb]     = fmaxf(c[2] + b0, 0.0f);
                Hs[(r0 + 8) * 132 + cb + 1] = fmaxf(c[3] + b1, 0.0f);
            }
    for (int i = tid; i < 645; i += 256) W2s[i] = (i < 640) ? __ldg(W2 + i) : __ldg(bl2 + i - 640);
    __syncthreads();

    if (tid < 128) {
        int e = e0 + tid;
        if (e < E) {
            float l[5];
#pragma unroll
            for (int q = 0; q < 5; q++) l[q] = W2s[640 + q];
#pragma unroll 4
            for (int k = 0; k < 128; k++) {
                float h = Hs[tid * 132 + k];
#pragma unroll
                for (int q = 0; q < 5; q++) l[q] += h * W2s[k * 5 + q];
            }
            float mx = l[0];
#pragma unroll
            for (int q = 1; q < 5; q++) mx = fmaxf(mx, l[q]);
            float s = 0.0f, ex[5];
#pragma unroll
            for (int q = 0; q < 5; q++) { ex[q] = expf(l[q] - mx); s += ex[q]; }
            float inv = 1.0f / s;
#pragma unroll
            for (int q = 0; q < 5; q++) out[e * 5 + q] = ex[q] * inv;
        }
    }
}

extern "C" void kernel_launch(void* const* d_in, const int* in_sizes, int n_in,
                              void* d_out, int out_size) {
    const float* x      = (const float*)d_in[0];
    const int*   tei    = (const int*)d_in[1];
    const int*   dei    = (const int*)d_in[2];
    const float* eattr  = (const float*)d_in[3];
    const float* Wroot1 = (const float*)d_in[4];
    const float* Wrel1  = (const float*)d_in[5];
    const float* b1     = (const float*)d_in[6];
    const float* Wroot2 = (const float*)d_in[7];
    const float* Wrel2  = (const float*)d_in[8];
    const float* b2     = (const float*)d_in[9];
    const float* W1     = (const float*)d_in[10];
    const float* bl1    = (const float*)d_in[11];
    const float* W2     = (const float*)d_in[12];
    const float* bl2    = (const float*)d_in[13];
    float* out = (float*)d_out;

    int Etr = in_sizes[1] / 2;
    int Ed  = in_sizes[2] / 2;

    static int smem_set = 0;
    if (!smem_set) {
        cudaFuncSetAttribute(decode_mma_k, cudaFuncAttributeMaxDynamicSharedMemorySize,
                             SMEM_DEC);
        cudaFuncSetAttribute(node1_mma_k, cudaFuncAttributeMaxDynamicSharedMemorySize,
                             N1_SMEM);
        smem_set = 1;
    }

    zero_k<<<(N_NODES * ZDIM + 255) / 256, 256>>>();
    prepB_k<<<(128 * 832 + 255) / 256, 256>>>(W1);
    prepW2_k<<<(128 * 128 + 255) / 256, 256>>>(Wrel2, Wroot2);
    edge1_k<<<(Etr + 255) / 256, 256>>>(tei, tei + Etr, x, Etr);
    node1_mma_k<<<(N_NODES + 63) / 64, 256, N1_SMEM>>>(x, Wroot1, Wrel1, b1);
    {
        long threads = (long)Etr * 16;
        edge2_k<<<(int)((threads + 255) / 256), 256>>>(tei, tei + Etr, Etr);
    }
    node2_k<<<(N_NODES * ZDIM + 255) / 256, 256>>>(b2);
    {
        long threads = (long)Ed * 16;
        pair_k<<<(int)((threads + 255) / 256), 256>>>(dei, dei + Ed, Ed);
    }
    decode_mma_k<<<(Ed + 127) / 128, 256, SMEM_DEC>>>(eattr, bl1, W2, bl2, out, Ed);
}